// round 7
// baseline (speedup 1.0000x reference)
#include <cuda_runtime.h>
#include <cuda_bf16.h>
#include <cstdint>

#define HD      50
#define BT      32          // batches per block (both teams cover all 32)
#define TT      512
#define NTH     448         // team A: warps 0-6 (layer0), team B: warps 7-13 (layer1)
#define TEAMTH  224
#define HSTR    36          // h row stride in floats
#define RINGD   8           // h0 ring depth (steps)

// smem float offsets
#define SM_W0   0           // [50][200]  gate-interleaved  (10000)
#define SM_W1   10000       // [100][200] gate-interleaved  (20000)
#define SM_H0R  30000       // h0 ring: RINGD x [50][36]    (14400)
#define SM_H1   44400       // h1 double buf: 2 x [50][36]  (3600)
#define SM_FLG  48000       // prod/cons counters (ints)
#define SM_TOTAL 48016      // floats -> 192064 bytes

// ---------------- packed f32x2 helpers ----------------
__device__ __forceinline__ unsigned long long dup2(float w) {
    unsigned long long r;
    asm("mov.b64 %0, {%1, %1};" : "=l"(r) : "f"(w));
    return r;
}
__device__ __forceinline__ unsigned long long pack2(float lo, float hi) {
    unsigned long long r;
    asm("mov.b64 %0, {%1, %2};" : "=l"(r) : "f"(lo), "f"(hi));
    return r;
}
__device__ __forceinline__ void fma2(unsigned long long &acc,
                                     unsigned long long a,
                                     unsigned long long b) {
    asm("fma.rn.f32x2 %0, %1, %2, %3;" : "=l"(acc) : "l"(a), "l"(b), "l"(acc));
}
__device__ __forceinline__ void unpack2(unsigned long long v, float &lo, float &hi) {
    asm("mov.b64 {%0, %1}, %2;" : "=f"(lo), "=f"(hi) : "l"(v));
}
__device__ __forceinline__ float tanhap(float x) {
    float y;
    asm("tanh.approx.f32 %0, %1;" : "=f"(y) : "f"(x));
    return y;
}
__device__ __forceinline__ float sigap(float x) {
    return 0.5f * tanhap(0.5f * x) + 0.5f;
}
__device__ __forceinline__ void team_bar(int id) {
    asm volatile("bar.sync %0, %1;" :: "r"(id), "r"(TEAMTH) : "memory");
}
__device__ __forceinline__ void spin_ge(volatile int* p, int want) {
    while (*p < want) { }
    asm volatile("" ::: "memory");   // no hoisting of LDS above the spin
}

// dense k-chunk (R2-proven): acc[j][p] += W[k][4u+j] * h[k][8bs + 2p..]
// 4 gates (j) x 8 batches (4 packed pairs). Per k: 3 LDS.128 + 4 MOV + 16 FFMA2.
__device__ __forceinline__ void mm_chunk(unsigned long long acc[4][4],
                                         const float* __restrict__ Wk,
                                         const float* __restrict__ hb,
                                         int u, int bs) {
#pragma unroll 5
    for (int k = 0; k < HD; k++) {
        float4 w = *reinterpret_cast<const float4*>(Wk + k * 200 + 4 * u);
        ulonglong2 ha = *reinterpret_cast<const ulonglong2*>(hb + k * HSTR + 8 * bs);
        ulonglong2 hc = *reinterpret_cast<const ulonglong2*>(hb + k * HSTR + 8 * bs + 4);
        unsigned long long w0 = dup2(w.x), w1 = dup2(w.y), w2 = dup2(w.z), w3 = dup2(w.w);
        fma2(acc[0][0], ha.x, w0); fma2(acc[0][1], ha.y, w0);
        fma2(acc[0][2], hc.x, w0); fma2(acc[0][3], hc.y, w0);
        fma2(acc[1][0], ha.x, w1); fma2(acc[1][1], ha.y, w1);
        fma2(acc[1][2], hc.x, w1); fma2(acc[1][3], hc.y, w1);
        fma2(acc[2][0], ha.x, w2); fma2(acc[2][1], ha.y, w2);
        fma2(acc[2][2], hc.x, w2); fma2(acc[2][3], hc.y, w2);
        fma2(acc[3][0], ha.x, w3); fma2(acc[3][1], ha.y, w3);
        fma2(acc[3][2], hc.x, w3); fma2(acc[3][3], hc.y, w3);
    }
}

// cell update for 8 batches; c in regs; writes 8 h floats
__device__ __forceinline__ void cell_update(unsigned long long acc[4][4],
                                            float c[8], float* __restrict__ hw) {
    float hn[8];
#pragma unroll
    for (int p = 0; p < 4; p++) {
        float il, ih, fl, fh, gl, gh, ol, oh;
        unpack2(acc[0][p], il, ih);
        unpack2(acc[1][p], fl, fh);
        unpack2(acc[2][p], gl, gh);
        unpack2(acc[3][p], ol, oh);
        {
            float i_ = sigap(il), f_ = sigap(fl), g_ = tanhap(gl), o_ = sigap(ol);
            float cv = f_ * c[2 * p] + i_ * g_;
            c[2 * p] = cv;
            hn[2 * p] = o_ * tanhap(cv);
        }
        {
            float i_ = sigap(ih), f_ = sigap(fh), g_ = tanhap(gh), o_ = sigap(oh);
            float cv = f_ * c[2 * p + 1] + i_ * g_;
            c[2 * p + 1] = cv;
            hn[2 * p + 1] = o_ * tanhap(cv);
        }
    }
    *reinterpret_cast<float4*>(hw)     = make_float4(hn[0], hn[1], hn[2], hn[3]);
    *reinterpret_cast<float4*>(hw + 4) = make_float4(hn[4], hn[5], hn[6], hn[7]);
}

__global__ __launch_bounds__(NTH, 1)
void lstm_pipe_kernel(const float* __restrict__ x,
                      const float* __restrict__ Wih0,
                      const float* __restrict__ Whh0,
                      const float* __restrict__ bih0,
                      const float* __restrict__ bhh0,
                      const float* __restrict__ Wih1,
                      const float* __restrict__ Whh1,
                      const float* __restrict__ bih1,
                      const float* __restrict__ bhh1,
                      const float* __restrict__ W1,
                      const float* __restrict__ b1,
                      const float* __restrict__ W2,
                      const float* __restrict__ b2,
                      const float* __restrict__ W3,
                      const float* __restrict__ b3,
                      float* __restrict__ out) {
    extern __shared__ float sm[];
    float* WT0  = sm + SM_W0;
    float* WT1  = sm + SM_W1;
    float* H0R  = sm + SM_H0R;   // ring slots of 1800 floats
    float* H1   = sm + SM_H1;    // 2 bufs of 1800
    volatile int* prod = (volatile int*)(sm + SM_FLG);
    volatile int* cons = (volatile int*)(sm + SM_FLG) + 1;

    const int tid  = threadIdx.x;
    const int b0   = blockIdx.x * BT;
    const int team = tid / TEAMTH;        // 0 = layer0 producer, 1 = layer1 consumer
    const int ttid = tid - team * TEAMTH;
    const bool act = (ttid < 200);
    const int u  = ttid >> 2;             // 0..49
    const int bs = ttid & 3;              // 0..3, 8 batches each

    // ---- prologue (all threads cooperate) ----
    for (int i = tid; i < 10000; i += NTH) {
        int r = i / HD, k = i % HD;
        int uu = r % HD, j = r / HD;
        WT0[k * 200 + 4 * uu + j] = Whh0[i];
    }
    for (int i = tid; i < 10000; i += NTH) {
        int r = i / HD, k = i % HD;
        int uu = r % HD, j = r / HD;
        WT1[k * 200 + 4 * uu + j]        = Wih1[i];
        WT1[(k + HD) * 200 + 4 * uu + j] = Whh1[i];
    }
    // zero ring slot RINGD-1 (h0 at t=-1) and both h1 buffers
    for (int i = tid; i < 1800; i += NTH) H0R[(RINGD - 1) * 1800 + i] = 0.0f;
    for (int i = tid; i < 3600; i += NTH) H1[i] = 0.0f;
    if (tid == 0) { *prod = 0; *cons = 0; }
    __syncthreads();

    if (team == 0) {
        // =================== TEAM A: layer-0 recurrence ===================
        unsigned long long bias0a = 0, bias0b = 0, bias0c = 0, bias0d = 0;
        unsigned long long wx0 = 0, wx1 = 0, wx2 = 0, wx3 = 0;
        float c0[8] = {0, 0, 0, 0, 0, 0, 0, 0};
        const float* xp = x + (size_t)(b0 + 8 * bs) * TT;
        float xf[8];
        if (act) {
            bias0a = dup2(bih0[u]       + bhh0[u]);
            bias0b = dup2(bih0[u + 50]  + bhh0[u + 50]);
            bias0c = dup2(bih0[u + 100] + bhh0[u + 100]);
            bias0d = dup2(bih0[u + 150] + bhh0[u + 150]);
            wx0 = dup2(Wih0[u]);       wx1 = dup2(Wih0[u + 50]);
            wx2 = dup2(Wih0[u + 100]); wx3 = dup2(Wih0[u + 150]);
#pragma unroll
            for (int i = 0; i < 8; i++) xf[i] = xp[(size_t)i * TT];
        }

        for (int t = 0; t < TT; t++) {
            const int rs = (t + RINGD - 1) & (RINGD - 1);   // slot of h0(t-1)
            const int ws = t & (RINGD - 1);                 // slot for h0(t)
            if (act) {
                unsigned long long acc[4][4];
#pragma unroll
                for (int p = 0; p < 4; p++) {
                    unsigned long long xb = pack2(xf[2 * p], xf[2 * p + 1]);
                    acc[0][p] = bias0a; fma2(acc[0][p], xb, wx0);
                    acc[1][p] = bias0b; fma2(acc[1][p], xb, wx1);
                    acc[2][p] = bias0c; fma2(acc[2][p], xb, wx2);
                    acc[3][p] = bias0d; fma2(acc[3][p], xb, wx3);
                }
                // prefetch next x (L2-resident; consumed next step)
                {
                    int tn = (t + 1) & (TT - 1);
#pragma unroll
                    for (int i = 0; i < 8; i++) xf[i] = xp[(size_t)i * TT + tn];
                }
                mm_chunk(acc, WT0, H0R + rs * 1800, u, bs);
                // ring backpressure: slot ws last used by step t-RINGD
                spin_ge(cons, t - RINGD + 1);
                cell_update(acc, c0, H0R + ws * 1800 + u * HSTR + 8 * bs);
            } else {
                spin_ge(cons, t - RINGD + 1);
            }
            team_bar(1);                 // h0(t) writes drained & team-wide done
            if (ttid == 0) *prod = t + 1;
        }
    } else {
        // =================== TEAM B: layer-1 recurrence ===================
        unsigned long long bias1a = 0, bias1b = 0, bias1c = 0, bias1d = 0;
        float c1[8] = {0, 0, 0, 0, 0, 0, 0, 0};
        if (act) {
            bias1a = dup2(bih1[u]       + bhh1[u]);
            bias1b = dup2(bih1[u + 50]  + bhh1[u + 50]);
            bias1c = dup2(bih1[u + 100] + bhh1[u + 100]);
            bias1d = dup2(bih1[u + 150] + bhh1[u + 150]);
        }

        for (int t = 0; t < TT; t++) {
            const int hs = t & (RINGD - 1);   // h0(t) slot
            const int rb = t & 1;             // h1(t-1) buffer
            const int wb = rb ^ 1;
            spin_ge(prod, t + 1);             // wait for h0(t)
            if (act) {
                unsigned long long acc[4][4];
#pragma unroll
                for (int p = 0; p < 4; p++) {
                    acc[0][p] = bias1a; acc[1][p] = bias1b;
                    acc[2][p] = bias1c; acc[3][p] = bias1d;
                }
                mm_chunk(acc, WT1,            H0R + hs * 1800, u, bs);
                mm_chunk(acc, WT1 + HD * 200, H1 + rb * 1800, u, bs);
                cell_update(acc, c1, H1 + wb * 1800 + u * HSTR + 8 * bs);
            }
            team_bar(2);                      // all reads of slot hs done
            if (ttid == 0) *cons = t + 1;
        }
    }

    __syncthreads();

    // ---- MLP head on final h1 (buffer (511&1)^1 = 0) ----
    const float* hf = H1;              // [k*HSTR + b]
    float* tmp1 = WT0;                 // scratch [32][33]
    float* tmp2 = WT0 + 1100;          // scratch [32][17]
    for (int item = tid; item < BT * 32; item += NTH) {
        int b = item >> 5;
        int o = item & 31;
        float s = b1[o];
#pragma unroll
        for (int k = 0; k < HD; k++) s += hf[k * HSTR + b] * W1[o * HD + k];
        tmp1[b * 33 + o] = fmaxf(s, 0.0f);
    }
    __syncthreads();
    for (int item = tid; item < BT * 16; item += NTH) {
        int b = item >> 4;
        int o = item & 15;
        float s = b2[o];
#pragma unroll
        for (int k = 0; k < 32; k++) s += tmp1[b * 33 + k] * W2[o * 32 + k];
        tmp2[b * 17 + o] = fmaxf(s, 0.0f);
    }
    __syncthreads();
    if (tid < BT) {
        float s = b3[0];
#pragma unroll
        for (int k = 0; k < 16; k++) s += tmp2[tid * 17 + k] * W3[k];
        out[b0 + tid] = s;
    }
}

extern "C" void kernel_launch(void* const* d_in, const int* in_sizes, int n_in,
                              void* d_out, int out_size) {
    const float* x    = (const float*)d_in[0];
    const float* Wih0 = (const float*)d_in[1];
    const float* Whh0 = (const float*)d_in[2];
    const float* bih0 = (const float*)d_in[3];
    const float* bhh0 = (const float*)d_in[4];
    const float* Wih1 = (const float*)d_in[5];
    const float* Whh1 = (const float*)d_in[6];
    const float* bih1 = (const float*)d_in[7];
    const float* bhh1 = (const float*)d_in[8];
    const float* W1   = (const float*)d_in[9];
    const float* b1   = (const float*)d_in[10];
    const float* W2   = (const float*)d_in[11];
    const float* b2   = (const float*)d_in[12];
    const float* W3   = (const float*)d_in[13];
    const float* b3   = (const float*)d_in[14];
    float* out = (float*)d_out;

    int B = in_sizes[0] / TT;
    int grid = B / BT;  // 128

    size_t smem_bytes = (size_t)SM_TOTAL * sizeof(float);  // 192064 B
    cudaFuncSetAttribute(lstm_pipe_kernel,
                         cudaFuncAttributeMaxDynamicSharedMemorySize,
                         (int)smem_bytes);

    lstm_pipe_kernel<<<grid, NTH, smem_bytes>>>(
        x, Wih0, Whh0, bih0, bhh0,
        Wih1, Whh1, bih1, bhh1,
        W1, b1, W2, b2, W3, b3, out);
}

// round 10
// speedup vs baseline: 1.2788x; 1.2788x over previous
#include <cuda_runtime.h>
#include <cuda_fp16.h>
#include <cstdint>

#define HD 50
#define BT 32
#define TT 512
#define NTH 448
#define W0S 72
#define W1S 120
#define H0S 72
#define HCS 120
#define GSS 36

#define O_W0HI 0
#define O_W0LO (O_W0HI + 208*W0S*2)
#define O_W1HI (O_W0LO + 208*W0S*2)
#define O_W1LO (O_W1HI + 208*W1S*2)
#define O_H0HI (O_W1LO + 208*W1S*2)
#define O_H0LO (O_H0HI + 32*H0S*2)
#define O_HCHI (O_H0LO + 32*H0S*2)
#define O_HCLO (O_HCHI + 32*HCS*2)
#define O_GS   (O_HCLO + 32*HCS*2)
#define O_XB   (O_GS + 208*GSS*4)
#define SMEM_REQ (O_XB + 256)

__device__ __forceinline__ float tanhap(float x) {
    float y; asm("tanh.approx.f32 %0, %1;" : "=f"(y) : "f"(x)); return y;
}
__device__ __forceinline__ float sigap(float x) { return 0.5f * tanhap(0.5f * x) + 0.5f; }
__device__ __forceinline__ uint32_t ld32h(const __half* p) { return *(const uint32_t*)p; }
__device__ __forceinline__ void hmma(float* d, uint32_t a0, uint32_t a1, uint32_t a2,
                                     uint32_t a3, uint32_t b0, uint32_t b1) {
    asm volatile("mma.sync.aligned.m16n8k16.row.col.f32.f16.f16.f32 "
        "{%0,%1,%2,%3}, {%4,%5,%6,%7}, {%8,%9}, {%0,%1,%2,%3};"
        : "+f"(d[0]), "+f"(d[1]), "+f"(d[2]), "+f"(d[3])
        : "r"(a0), "r"(a1), "r"(a2), "r"(a3), "r"(b0), "r"(b1));
}

// D[nt] += Whi@(Hhi+Hlo) + Wlo@Hhi over nch k16 chunks
__device__ __forceinline__ void mma_phase(const __half* Whi, const __half* Wlo, int ws,
                                          const __half* Hhi, const __half* Hlo, int hs,
                                          int nch, float (&D)[4][4], int g, int tg, int warp) {
    const __half* wh = Whi + (warp * 16 + g) * ws + 2 * tg;
    const __half* wl = Wlo + (warp * 16 + g) * ws + 2 * tg;
    const __half* hh = Hhi + g * hs + 2 * tg;
    const __half* hl = Hlo + g * hs + 2 * tg;
#pragma unroll 1
    for (int c = 0; c < nch; c++) {
        const int k0 = 16 * c;
        uint32_t ah0 = ld32h(wh + k0),            ah1 = ld32h(wh + 8 * ws + k0);
        uint32_t ah2 = ld32h(wh + k0 + 8),        ah3 = ld32h(wh + 8 * ws + k0 + 8);
        uint32_t al0 = ld32h(wl + k0),            al1 = ld32h(wl + 8 * ws + k0);
        uint32_t al2 = ld32h(wl + k0 + 8),        al3 = ld32h(wl + 8 * ws + k0 + 8);
#pragma unroll
        for (int nt = 0; nt < 4; nt++) {
            uint32_t bh0 = ld32h(hh + nt * 8 * hs + k0), bh1 = ld32h(hh + nt * 8 * hs + k0 + 8);
            uint32_t bl0 = ld32h(hl + nt * 8 * hs + k0), bl1 = ld32h(hl + nt * 8 * hs + k0 + 8);
            hmma(D[nt], ah0, ah1, ah2, ah3, bh0, bh1);
            hmma(D[nt], ah0, ah1, ah2, ah3, bl0, bl1);
            hmma(D[nt], al0, al1, al2, al3, bh0, bh1);
        }
    }
}

__device__ __forceinline__ void store_D(float* Gs, float (&D)[4][4], int g, int tg, int warp) {
#pragma unroll
    for (int nt = 0; nt < 4; nt++) {
        int col = 8 * nt + 2 * tg;
        *(float2*)(Gs + (warp * 16 + g) * GSS + col)     = make_float2(D[nt][0], D[nt][1]);
        *(float2*)(Gs + (warp * 16 + g + 8) * GSS + col) = make_float2(D[nt][2], D[nt][3]);
    }
}

__global__ __launch_bounds__(NTH, 1)
void lstm_hmma_kernel(const float* __restrict__ x,
                      const float* __restrict__ Wih0, const float* __restrict__ Whh0,
                      const float* __restrict__ bih0, const float* __restrict__ bhh0,
                      const float* __restrict__ Wih1, const float* __restrict__ Whh1,
                      const float* __restrict__ bih1, const float* __restrict__ bhh1,
                      const float* __restrict__ W1, const float* __restrict__ b1,
                      const float* __restrict__ W2, const float* __restrict__ b2,
                      const float* __restrict__ W3, const float* __restrict__ b3,
                      float* __restrict__ out) {
    extern __shared__ char sm[];
    __half* W0hi = (__half*)(sm + O_W0HI);
    __half* W0lo = (__half*)(sm + O_W0LO);
    __half* W1hi = (__half*)(sm + O_W1HI);
    __half* W1lo = (__half*)(sm + O_W1LO);
    __half* H0hi = (__half*)(sm + O_H0HI);
    __half* H0lo = (__half*)(sm + O_H0LO);
    __half* HChi = (__half*)(sm + O_HCHI);
    __half* HClo = (__half*)(sm + O_HCLO);
    float*  Gs   = (float*)(sm + O_GS);
    float*  xb   = (float*)(sm + O_XB);

    const int tid = threadIdx.x, lane = tid & 31, warp = tid >> 5;
    const int g = lane >> 2, tg = lane & 3;
    const int b0 = blockIdx.x * BT;

    // ---- pack W0 (rows r=4u+j, k<50) fp16 hi/lo ----
    for (int i = tid; i < 208 * 64; i += NTH) {
        int r = i >> 6, k = i & 63;
        float v = 0.0f;
        if (r < 200 && k < HD) v = Whh0[(size_t)((r & 3) * HD + (r >> 2)) * HD + k];
        __half hi = __float2half_rn(v);
        W0hi[r * W0S + k] = hi;
        W0lo[r * W0S + k] = __float2half_rn(v - __half2float(hi));
    }
    // ---- pack W1 = [Wih1 | Whh1] rows 4u+j, k<100, stride 120 ----
    for (int i = tid; i < 208 * 128; i += NTH) {
        int r = i >> 7, k = i & 127;
        if (k >= W1S) continue;
        float v = 0.0f;
        if (r < 200 && k < 100) {
            int row = (r & 3) * HD + (r >> 2);
            v = (k < HD) ? Wih1[(size_t)row * HD + k] : Whh1[(size_t)row * HD + (k - HD)];
        }
        __half hi = __float2half_rn(v);
        W1hi[r * W1S + k] = hi;
        W1lo[r * W1S + k] = __float2half_rn(v - __half2float(hi));
    }
    // ---- zero h buffers; x slot 0 ----
    for (int i = tid; i < 32 * H0S; i += NTH) { H0hi[i] = __half(0.f); H0lo[i] = __half(0.f); }
    for (int i = tid; i < 32 * HCS; i += NTH) { HChi[i] = __half(0.f); HClo[i] = __half(0.f); }
    if (tid < 32) xb[tid] = x[(size_t)(b0 + tid) * TT];

    // cell-thread constants
    const int u = tid >> 2, bs = tid & 3;
    const bool cellth = (tid < 200);
    float bias0[4], bias1[4], wx[4];
    if (cellth) {
#pragma unroll
        for (int j = 0; j < 4; j++) {
            int r = j * HD + u;
            bias0[j] = bih0[r] + bhh0[r];
            bias1[j] = bih1[r] + bhh1[r];
            wx[j]    = Wih0[r];
        }
    }
    float c0[8] = {0,0,0,0,0,0,0,0}, c1[8] = {0,0,0,0,0,0,0,0};
    __syncthreads();

    for (int t = 0; t < TT; t++) {
        // ===== phase 0: layer-0 MMA =====
        if (warp < 13) {
            float D[4][4] = {};
            mma_phase(W0hi, W0lo, W0S, H0hi, H0lo, H0S, 4, D, g, tg, warp);
            store_D(Gs, D, g, tg, warp);
        } else if (t + 1 < TT) {
            xb[((t + 1) & 1) * 32 + lane] = x[(size_t)(b0 + lane) * TT + (t + 1)];
        }
        __syncthreads();
        // ===== epi 0 =====
        if (cellth) {
            const float* xr = xb + (t & 1) * 32 + 8 * bs;
#pragma unroll
            for (int i = 0; i < 8; i++) {
                int b = 8 * bs + i;
                float xv = xr[i];
                float gi = Gs[(4 * u + 0) * GSS + b] + bias0[0] + wx[0] * xv;
                float gf = Gs[(4 * u + 1) * GSS + b] + bias0[1] + wx[1] * xv;
                float gg = Gs[(4 * u + 2) * GSS + b] + bias0[2] + wx[2] * xv;
                float go = Gs[(4 * u + 3) * GSS + b] + bias0[3] + wx[3] * xv;
                float cv = sigap(gf) * c0[i] + sigap(gi) * tanhap(gg);
                c0[i] = cv;
                float hv = sigap(go) * tanhap(cv);
                __half hi = __float2half_rn(hv);
                __half lo = __float2half_rn(hv - __half2float(hi));
                H0hi[b * H0S + u] = hi;  H0lo[b * H0S + u] = lo;
                HChi[b * HCS + u] = hi;  HClo[b * HCS + u] = lo;
            }
        }
        __syncthreads();
        // ===== phase 1: layer-1 MMA (K = [h0(t) | h1(t-1)]) =====
        if (warp < 13) {
            float D[4][4] = {};
            mma_phase(W1hi, W1lo, W1S, HChi, HClo, HCS, 7, D, g, tg, warp);
            store_D(Gs, D, g, tg, warp);
        }
        __syncthreads();
        // ===== epi 1 =====
        if (cellth) {
#pragma unroll
            for (int i = 0; i < 8; i++) {
                int b = 8 * bs + i;
                float gi = Gs[(4 * u + 0) * GSS + b] + bias1[0];
                float gf = Gs[(4 * u + 1) * GSS + b] + bias1[1];
                float gg = Gs[(4 * u + 2) * GSS + b] + bias1[2];
                float go = Gs[(4 * u + 3) * GSS + b] + bias1[3];
                float cv = sigap(gf) * c1[i] + sigap(gi) * tanhap(gg);
                c1[i] = cv;
                float hv = sigap(go) * tanhap(cv);
                __half hi = __float2half_rn(hv);
                __half lo = __float2half_rn(hv - __half2float(hi));
                HChi[b * HCS + HD + u] = hi;  HClo[b * HCS + HD + u] = lo;
            }
        }
        __syncthreads();
    }

    // ---- MLP head on h1(511) from HC cols 50..99 ----
    float* tmp1 = Gs;            // [32][33]
    float* tmp2 = Gs + 1100;     // [32][17]
    for (int item = tid; item < BT * 32; item += NTH) {
        int b = item >> 5, o = item & 31;
        float s = b1[o];
#pragma unroll 1
        for (int k = 0; k < HD; k++) {
            float h = __half2float(HChi[b * HCS + HD + k]) + __half2float(HClo[b * HCS + HD + k]);
            s += h * W1[o * HD + k];
        }
        tmp1[b * 33 + o] = fmaxf(s, 0.0f);
    }
    __syncthreads();
    for (int item = tid; item < BT * 16; item += NTH) {
        int b = item >> 4, o = item & 15;
        float s = b2[o];
#pragma unroll
        for (int k = 0; k < 32; k++) s += tmp1[b * 33 + k] * W2[o * 32 + k];
        tmp2[b * 17 + o] = fmaxf(s, 0.0f);
    }
    __syncthreads();
    if (tid < BT) {
        float s = b3[0];
#pragma unroll
        for (int k = 0; k < 16; k++) s += tmp2[tid * 17 + k] * W3[k];
        out[b0 + tid] = s;
    }
}

extern "C" void kernel_launch(void* const* d_in, const int* in_sizes, int n_in,
                              void* d_out, int out_size) {
    const float* x    = (const float*)d_in[0];
    const float* Wih0 = (const float*)d_in[1];
    const float* Whh0 = (const float*)d_in[2];
    const float* bih0 = (const float*)d_in[3];
    const float* bhh0 = (const float*)d_in[4];
    const float* Wih1 = (const float*)d_in[5];
    const float* Whh1 = (const float*)d_in[6];
    const float* bih1 = (const float*)d_in[7];
    const float* bhh1 = (const float*)d_in[8];
    const float* W1   = (const float*)d_in[9];
    const float* b1   = (const float*)d_in[10];
    const float* W2   = (const float*)d_in[11];
    const float* b2   = (const float*)d_in[12];
    const float* W3   = (const float*)d_in[13];
    const float* b3   = (const float*)d_in[14];
    float* out = (float*)d_out;

    int B = in_sizes[0] / TT;
    int grid = B / BT;  // 128

    cudaFuncSetAttribute(lstm_hmma_kernel,
                         cudaFuncAttributeMaxDynamicSharedMemorySize, SMEM_REQ);
    lstm_hmma_kernel<<<grid, NTH, SMEM_REQ>>>(
        x, Wih0, Whh0, bih0, bhh0,
        Wih1, Whh1, bih1, bhh1,
        W1, b1, W2, b2, W3, b3, out);
}

// round 11
// speedup vs baseline: 1.8719x; 1.4638x over previous
#include <cuda_runtime.h>
#include <cuda_fp16.h>
#include <cstdint>

#define HD 50
#define BT 32
#define TT 512
#define NTH 448
#define W0S 72
#define W1S 120
#define HCS 120
#define GSS 33

#define O_W0HI 0
#define O_W0LO 29952
#define O_W1HI 59904
#define O_W1LO 109824
#define O_HCHI 159744
#define O_GS   167424
#define O_XB   194880
#define SMEM_REQ 195136

__device__ __forceinline__ float tanhap(float x) {
    float y; asm("tanh.approx.f32 %0, %1;" : "=f"(y) : "f"(x)); return y;
}
__device__ __forceinline__ float sigap(float x) { return 0.5f * tanhap(0.5f * x) + 0.5f; }
__device__ __forceinline__ uint32_t ld32h(const __half* p) { return *(const uint32_t*)p; }
__device__ __forceinline__ void hmma(float* d, uint32_t a0, uint32_t a1, uint32_t a2,
                                     uint32_t a3, uint32_t b0, uint32_t b1) {
    asm volatile("mma.sync.aligned.m16n8k16.row.col.f32.f16.f16.f32 "
        "{%0,%1,%2,%3}, {%4,%5,%6,%7}, {%8,%9}, {%0,%1,%2,%3};"
        : "+f"(d[0]), "+f"(d[1]), "+f"(d[2]), "+f"(d[3])
        : "r"(a0), "r"(a1), "r"(a2), "r"(a3), "r"(b0), "r"(b1));
}

// D[nt] += (Whi + Wlo) @ Hhi over nch k16 chunks (h single-fp16)
__device__ __forceinline__ void mma_phase(const __half* Whi, const __half* Wlo, int ws,
                                          const __half* Hhi, int hs, int nch,
                                          float (&D)[4][4], int g, int tg, int warp) {
    const __half* wh = Whi + (warp * 16 + g) * ws + 2 * tg;
    const __half* wl = Wlo + (warp * 16 + g) * ws + 2 * tg;
    const __half* hh = Hhi + g * hs + 2 * tg;
#pragma unroll 1
    for (int c = 0; c < nch; c++) {
        const int k0 = 16 * c;
        uint32_t ah0 = ld32h(wh + k0),     ah1 = ld32h(wh + 8 * ws + k0);
        uint32_t ah2 = ld32h(wh + k0 + 8), ah3 = ld32h(wh + 8 * ws + k0 + 8);
        uint32_t al0 = ld32h(wl + k0),     al1 = ld32h(wl + 8 * ws + k0);
        uint32_t al2 = ld32h(wl + k0 + 8), al3 = ld32h(wl + 8 * ws + k0 + 8);
#pragma unroll
        for (int nt = 0; nt < 4; nt++) {
            uint32_t b0 = ld32h(hh + nt * 8 * hs + k0), b1 = ld32h(hh + nt * 8 * hs + k0 + 8);
            hmma(D[nt], ah0, ah1, ah2, ah3, b0, b1);
            hmma(D[nt], al0, al1, al2, al3, b0, b1);
        }
    }
}

__device__ __forceinline__ void store_D(float* Gs, float (&D)[4][4], int g, int tg, int warp) {
#pragma unroll
    for (int nt = 0; nt < 4; nt++) {
        int col = 8 * nt + 2 * tg;
        int r0 = (warp * 16 + g) * GSS, r1 = (warp * 16 + g + 8) * GSS;
        Gs[r0 + col] = D[nt][0]; Gs[r0 + col + 1] = D[nt][1];
        Gs[r1 + col] = D[nt][2]; Gs[r1 + col + 1] = D[nt][3];
    }
}

__global__ __launch_bounds__(NTH, 1)
void lstm_hmma2_kernel(const float* __restrict__ x,
                       const float* __restrict__ Wih0, const float* __restrict__ Whh0,
                       const float* __restrict__ bih0, const float* __restrict__ bhh0,
                       const float* __restrict__ Wih1, const float* __restrict__ Whh1,
                       const float* __restrict__ bih1, const float* __restrict__ bhh1,
                       const float* __restrict__ W1, const float* __restrict__ b1,
                       const float* __restrict__ W2, const float* __restrict__ b2,
                       const float* __restrict__ W3, const float* __restrict__ b3,
                       float* __restrict__ out) {
    extern __shared__ char sm[];
    __half* W0hi = (__half*)(sm + O_W0HI);
    __half* W0lo = (__half*)(sm + O_W0LO);
    __half* W1hi = (__half*)(sm + O_W1HI);
    __half* W1lo = (__half*)(sm + O_W1LO);
    __half* HChi = (__half*)(sm + O_HCHI);
    float*  Gs   = (float*)(sm + O_GS);
    float*  xb   = (float*)(sm + O_XB);

    const int tid = threadIdx.x, lane = tid & 31, warp = tid >> 5;
    const int g = lane >> 2, tg = lane & 3;
    const int b0 = blockIdx.x * BT;

    // ---- pack W0 (rows r=4u+j, k<50) fp16 hi/lo; cols 50-63 zero ----
    for (int i = tid; i < 208 * 64; i += NTH) {
        int r = i >> 6, k = i & 63;
        float v = 0.0f;
        if (r < 200 && k < HD) v = Whh0[(size_t)((r & 3) * HD + (r >> 2)) * HD + k];
        __half hi = __float2half_rn(v);
        W0hi[r * W0S + k] = hi;
        W0lo[r * W0S + k] = __float2half_rn(v - __half2float(hi));
    }
    // ---- pack W1 = [Wih1 | Whh1] rows 4u+j, cols 100-119 zero ----
    for (int i = tid; i < 208 * 128; i += NTH) {
        int r = i >> 7, k = i & 127;
        if (k >= W1S) continue;
        float v = 0.0f;
        if (r < 200 && k < 100) {
            int row = (r & 3) * HD + (r >> 2);
            v = (k < HD) ? Wih1[(size_t)row * HD + k] : Whh1[(size_t)row * HD + (k - HD)];
        }
        __half hi = __float2half_rn(v);
        W1hi[r * W1S + k] = hi;
        W1lo[r * W1S + k] = __float2half_rn(v - __half2float(hi));
    }
    for (int i = tid; i < 32 * HCS; i += NTH) HChi[i] = __half(0.f);
    if (tid < 32) xb[tid] = x[(size_t)(b0 + tid) * TT];

    // cell threads: (u, bs) with batches b = bs + 4i  -> conflict-free Gs reads
    const int u = tid >> 2, bs = tid & 3;
    const bool cellth = (tid < 200);
    float bias0[4], bias1[4], wx[4];
    if (cellth) {
#pragma unroll
        for (int j = 0; j < 4; j++) {
            int r = j * HD + u;
            bias0[j] = bih0[r] + bhh0[r];
            bias1[j] = bih1[r] + bhh1[r];
            wx[j]    = Wih0[r];
        }
    }
    float c0[8] = {0,0,0,0,0,0,0,0}, c1[8] = {0,0,0,0,0,0,0,0};
    __syncthreads();

    for (int t = 0; t < TT; t++) {
        // ===== layer-0 MMA: B = HC cols 0..63 (W0 zero beyond k=50) =====
        if (warp < 13) {
            float D[4][4] = {};
            mma_phase(W0hi, W0lo, W0S, HChi, HCS, 4, D, g, tg, warp);
            store_D(Gs, D, g, tg, warp);
        } else if (t + 1 < TT) {
            xb[((t + 1) & 1) * 32 + lane] = x[(size_t)(b0 + lane) * TT + (t + 1)];
        }
        __syncthreads();
        if (cellth) {
            const float* xr = xb + (t & 1) * 32;
#pragma unroll
            for (int i = 0; i < 8; i++) {
                int b = bs + 4 * i;
                float xv = xr[b];
                float gi = Gs[(4 * u + 0) * GSS + b] + bias0[0] + wx[0] * xv;
                float gf = Gs[(4 * u + 1) * GSS + b] + bias0[1] + wx[1] * xv;
                float gg = Gs[(4 * u + 2) * GSS + b] + bias0[2] + wx[2] * xv;
                float go = Gs[(4 * u + 3) * GSS + b] + bias0[3] + wx[3] * xv;
                float cv = sigap(gf) * c0[i] + sigap(gi) * tanhap(gg);
                c0[i] = cv;
                HChi[b * HCS + u] = __float2half_rn(sigap(go) * tanhap(cv));
            }
        }
        __syncthreads();
        // ===== layer-1 MMA: B = HC cols 0..111 (h0 | h1 | zero-pad) =====
        if (warp < 13) {
            float D[4][4] = {};
            mma_phase(W1hi, W1lo, W1S, HChi, HCS, 7, D, g, tg, warp);
            store_D(Gs, D, g, tg, warp);
        }
        __syncthreads();
        if (cellth) {
#pragma unroll
            for (int i = 0; i < 8; i++) {
                int b = bs + 4 * i;
                float gi = Gs[(4 * u + 0) * GSS + b] + bias1[0];
                float gf = Gs[(4 * u + 1) * GSS + b] + bias1[1];
                float gg = Gs[(4 * u + 2) * GSS + b] + bias1[2];
                float go = Gs[(4 * u + 3) * GSS + b] + bias1[3];
                float cv = sigap(gf) * c1[i] + sigap(gi) * tanhap(gg);
                c1[i] = cv;
                HChi[b * HCS + HD + u] = __float2half_rn(sigap(go) * tanhap(cv));
            }
        }
        __syncthreads();
    }

    // ---- MLP head on h1(511) = HC cols 50..99 ----
    float* tmp1 = Gs;            // [32][33]
    float* tmp2 = Gs + 1100;     // [32][17]
    for (int item = tid; item < BT * 32; item += NTH) {
        int b = item >> 5, o = item & 31;
        float s = b1[o];
#pragma unroll 1
        for (int k = 0; k < HD; k++)
            s += __half2float(HChi[b * HCS + HD + k]) * W1[o * HD + k];
        tmp1[b * 33 + o] = fmaxf(s, 0.0f);
    }
    __syncthreads();
    for (int item = tid; item < BT * 16; item += NTH) {
        int b = item >> 4, o = item & 15;
        float s = b2[o];
#pragma unroll
        for (int k = 0; k < 32; k++) s += tmp1[b * 33 + k] * W2[o * 32 + k];
        tmp2[b * 17 + o] = fmaxf(s, 0.0f);
    }
    __syncthreads();
    if (tid < BT) {
        float s = b3[0];
#pragma unroll
        for (int k = 0; k < 16; k++) s += tmp2[tid * 17 + k] * W3[k];
        out[b0 + tid] = s;
    }
}

extern "C" void kernel_launch(void* const* d_in, const int* in_sizes, int n_in,
                              void* d_out, int out_size) {
    const float* x    = (const float*)d_in[0];
    const float* Wih0 = (const float*)d_in[1];
    const float* Whh0 = (const float*)d_in[2];
    const float* bih0 = (const float*)d_in[3];
    const float* bhh0 = (const float*)d_in[4];
    const float* Wih1 = (const float*)d_in[5];
    const float* Whh1 = (const float*)d_in[6];
    const float* bih1 = (const float*)d_in[7];
    const float* bhh1 = (const float*)d_in[8];
    const float* W1   = (const float*)d_in[9];
    const float* b1   = (const float*)d_in[10];
    const float* W2   = (const float*)d_in[11];
    const float* b2   = (const float*)d_in[12];
    const float* W3   = (const float*)d_in[13];
    const float* b3   = (const float*)d_in[14];
    float* out = (float*)d_out;

    int B = in_sizes[0] / TT;
    int grid = B / BT;  // 128

    cudaFuncSetAttribute(lstm_hmma2_kernel,
                         cudaFuncAttributeMaxDynamicSharedMemorySize, SMEM_REQ);
    lstm_hmma2_kernel<<<grid, NTH, SMEM_REQ>>>(
        x, Wih0, Whh0, bih0, bhh0,
        Wih1, Whh1, bih1, bhh1,
        W1, b1, W2, b2, W3, b3, out);
}

// round 12
// speedup vs baseline: 2.0122x; 1.0750x over previous
#include <cuda_runtime.h>
#include <cuda_fp16.h>
#include <cstdint>

#define HD 50
#define BT 32
#define TT 512
#define NTH 448
#define W0S 72
#define W1S 120
#define HCS 120
#define GSS 33

#define O_W0HI 0
#define O_W0LO 29952
#define O_W1HI 59904
#define O_W1LO 109824
#define O_HCHI 159744
#define O_GS   167424
#define O_XB   194880
#define SMEM_REQ 195136

__device__ __forceinline__ float tanhap(float x) {
    float y; asm("tanh.approx.f32 %0, %1;" : "=f"(y) : "f"(x)); return y;
}
__device__ __forceinline__ float sigap(float x) { return 0.5f * tanhap(0.5f * x) + 0.5f; }
__device__ __forceinline__ uint32_t ld32h(const __half* p) { return *(const uint32_t*)p; }
__device__ __forceinline__ void hmma(float* d, uint32_t a0, uint32_t a1, uint32_t a2,
                                     uint32_t a3, uint32_t b0, uint32_t b1) {
    asm volatile("mma.sync.aligned.m16n8k16.row.col.f32.f16.f16.f32 "
        "{%0,%1,%2,%3}, {%4,%5,%6,%7}, {%8,%9}, {%0,%1,%2,%3};"
        : "+f"(d[0]), "+f"(d[1]), "+f"(d[2]), "+f"(d[3])
        : "r"(a0), "r"(a1), "r"(a2), "r"(a3), "r"(b0), "r"(b1));
}
__device__ __forceinline__ void store_D(float* Gs, float (&D)[4][4], int g, int tg, int warp) {
#pragma unroll
    for (int nt = 0; nt < 4; nt++) {
        int col = 8 * nt + 2 * tg;
        int r0 = (warp * 16 + g) * GSS, r1 = (warp * 16 + g + 8) * GSS;
        Gs[r0 + col] = D[nt][0]; Gs[r0 + col + 1] = D[nt][1];
        Gs[r1 + col] = D[nt][2]; Gs[r1 + col + 1] = D[nt][3];
    }
}

__global__ __launch_bounds__(NTH, 1)
void lstm_hmma3_kernel(const float* __restrict__ x,
                       const float* __restrict__ Wih0, const float* __restrict__ Whh0,
                       const float* __restrict__ bih0, const float* __restrict__ bhh0,
                       const float* __restrict__ Wih1, const float* __restrict__ Whh1,
                       const float* __restrict__ bih1, const float* __restrict__ bhh1,
                       const float* __restrict__ W1, const float* __restrict__ b1,
                       const float* __restrict__ W2, const float* __restrict__ b2,
                       const float* __restrict__ W3, const float* __restrict__ b3,
                       float* __restrict__ out) {
    extern __shared__ char sm[];
    __half* W0hi = (__half*)(sm + O_W0HI);
    __half* W0lo = (__half*)(sm + O_W0LO);
    __half* W1hi = (__half*)(sm + O_W1HI);
    __half* W1lo = (__half*)(sm + O_W1LO);
    __half* HChi = (__half*)(sm + O_HCHI);
    float*  Gs   = (float*)(sm + O_GS);
    float*  xb   = (float*)(sm + O_XB);

    const int tid = threadIdx.x, lane = tid & 31, warp = tid >> 5;
    const int g = lane >> 2, tg = lane & 3;
    const int b0 = blockIdx.x * BT;

    // ---- pack W0 / W1 fp16 hi/lo into smem (rows r = 4u+j) ----
    for (int i = tid; i < 208 * 64; i += NTH) {
        int r = i >> 6, k = i & 63;
        float v = 0.0f;
        if (r < 200 && k < HD) v = Whh0[(size_t)((r & 3) * HD + (r >> 2)) * HD + k];
        __half hi = __float2half_rn(v);
        W0hi[r * W0S + k] = hi;
        W0lo[r * W0S + k] = __float2half_rn(v - __half2float(hi));
    }
    for (int i = tid; i < 208 * 128; i += NTH) {
        int r = i >> 7, k = i & 127;
        if (k >= W1S) continue;
        float v = 0.0f;
        if (r < 200 && k < 100) {
            int row = (r & 3) * HD + (r >> 2);
            v = (k < HD) ? Wih1[(size_t)row * HD + k] : Whh1[(size_t)row * HD + (k - HD)];
        }
        __half hi = __float2half_rn(v);
        W1hi[r * W1S + k] = hi;
        W1lo[r * W1S + k] = __float2half_rn(v - __half2float(hi));
    }
    for (int i = tid; i < 32 * HCS; i += NTH) HChi[i] = __half(0.f);
    if (tid < 32) xb[tid] = x[(size_t)(b0 + tid) * TT];

    const int u = tid >> 2, bs = tid & 3;
    const bool cellth = (tid < 200);
    float bias0[4], bias1[4], wx[4];
    if (cellth) {
#pragma unroll
        for (int j = 0; j < 4; j++) {
            int r = j * HD + u;
            bias0[j] = bih0[r] + bhh0[r];
            bias1[j] = bih1[r] + bhh1[r];
            wx[j]    = Wih0[r];
        }
    }
    float c0[8] = {0,0,0,0,0,0,0,0}, c1[8] = {0,0,0,0,0,0,0,0};
    __syncthreads();

    // ---- hoist A fragments into registers (time-invariant) ----
    uint32_t A0h[4][4], A0l[4][4], A1h[7][4];
    if (warp < 13) {
        const __half* wh = W0hi + (warp * 16 + g) * W0S + 2 * tg;
        const __half* wl = W0lo + (warp * 16 + g) * W0S + 2 * tg;
#pragma unroll
        for (int c = 0; c < 4; c++) {
            int k0 = 16 * c;
            A0h[c][0] = ld32h(wh + k0);     A0h[c][1] = ld32h(wh + 8 * W0S + k0);
            A0h[c][2] = ld32h(wh + k0 + 8); A0h[c][3] = ld32h(wh + 8 * W0S + k0 + 8);
            A0l[c][0] = ld32h(wl + k0);     A0l[c][1] = ld32h(wl + 8 * W0S + k0);
            A0l[c][2] = ld32h(wl + k0 + 8); A0l[c][3] = ld32h(wl + 8 * W0S + k0 + 8);
        }
        const __half* w1 = W1hi + (warp * 16 + g) * W1S + 2 * tg;
#pragma unroll
        for (int c = 0; c < 7; c++) {
            int k0 = 16 * c;
            A1h[c][0] = ld32h(w1 + k0);     A1h[c][1] = ld32h(w1 + 8 * W1S + k0);
            A1h[c][2] = ld32h(w1 + k0 + 8); A1h[c][3] = ld32h(w1 + 8 * W1S + k0 + 8);
        }
    }
    const __half* hB  = HChi + g * HCS + 2 * tg;           // B fragment base
    const __half* w1l = W1lo + (warp * 16 + g) * W1S + 2 * tg;

    for (int t = 0; t < TT; t++) {
        // ===== layer-0 MMA (A in regs) =====
        if (warp < 13) {
            float D[4][4] = {};
#pragma unroll
            for (int c = 0; c < 4; c++) {
                int k0 = 16 * c;
#pragma unroll
                for (int nt = 0; nt < 4; nt++) {
                    uint32_t b0f = ld32h(hB + nt * 8 * HCS + k0);
                    uint32_t b1f = ld32h(hB + nt * 8 * HCS + k0 + 8);
                    hmma(D[nt], A0h[c][0], A0h[c][1], A0h[c][2], A0h[c][3], b0f, b1f);
                    hmma(D[nt], A0l[c][0], A0l[c][1], A0l[c][2], A0l[c][3], b0f, b1f);
                }
            }
            store_D(Gs, D, g, tg, warp);
        } else if (t + 1 < TT) {
            xb[((t + 1) & 1) * 32 + lane] = x[(size_t)(b0 + lane) * TT + (t + 1)];
        }
        __syncthreads();
        if (cellth) {
            const float* xr = xb + (t & 1) * 32;
#pragma unroll
            for (int i = 0; i < 8; i++) {
                int b = bs + 4 * i;
                float xv = xr[b];
                float gi = Gs[(4 * u + 0) * GSS + b] + bias0[0] + wx[0] * xv;
                float gf = Gs[(4 * u + 1) * GSS + b] + bias0[1] + wx[1] * xv;
                float gg = Gs[(4 * u + 2) * GSS + b] + bias0[2] + wx[2] * xv;
                float go = Gs[(4 * u + 3) * GSS + b] + bias0[3] + wx[3] * xv;
                float cv = sigap(gf) * c0[i] + sigap(gi) * tanhap(gg);
                c0[i] = cv;
                HChi[b * HCS + u] = __float2half_rn(sigap(go) * tanhap(cv));
            }
        }
        __syncthreads();
        // ===== layer-1 MMA (A-hi in regs, A-lo from smem) =====
        if (warp < 13) {
            float D[4][4] = {};
#pragma unroll
            for (int c = 0; c < 7; c++) {
                int k0 = 16 * c;
                uint32_t al0 = ld32h(w1l + k0),     al1 = ld32h(w1l + 8 * W1S + k0);
                uint32_t al2 = ld32h(w1l + k0 + 8), al3 = ld32h(w1l + 8 * W1S + k0 + 8);
#pragma unroll
                for (int nt = 0; nt < 4; nt++) {
                    uint32_t b0f = ld32h(hB + nt * 8 * HCS + k0);
                    uint32_t b1f = ld32h(hB + nt * 8 * HCS + k0 + 8);
                    hmma(D[nt], A1h[c][0], A1h[c][1], A1h[c][2], A1h[c][3], b0f, b1f);
                    hmma(D[nt], al0, al1, al2, al3, b0f, b1f);
                }
            }
            store_D(Gs, D, g, tg, warp);
        }
        __syncthreads();
        if (cellth) {
#pragma unroll
            for (int i = 0; i < 8; i++) {
                int b = bs + 4 * i;
                float gi = Gs[(4 * u + 0) * GSS + b] + bias1[0];
                float gf = Gs[(4 * u + 1) * GSS + b] + bias1[1];
                float gg = Gs[(4 * u + 2) * GSS + b] + bias1[2];
                float go = Gs[(4 * u + 3) * GSS + b] + bias1[3];
                float cv = sigap(gf) * c1[i] + sigap(gi) * tanhap(gg);
                c1[i] = cv;
                HChi[b * HCS + HD + u] = __float2half_rn(sigap(go) * tanhap(cv));
            }
        }
        __syncthreads();
    }

    // ---- MLP head on h1(511) = HC cols 50..99 ----
    float* tmp1 = Gs;
    float* tmp2 = Gs + 1100;
    for (int item = tid; item < BT * 32; item += NTH) {
        int b = item >> 5, o = item & 31;
        float s = b1[o];
#pragma unroll 1
        for (int k = 0; k < HD; k++)
            s += __half2float(HChi[b * HCS + HD + k]) * W1[o * HD + k];
        tmp1[b * 33 + o] = fmaxf(s, 0.0f);
    }
    __syncthreads();
    for (int item = tid; item < BT * 16; item += NTH) {
        int b = item >> 4, o = item & 15;
        float s = b2[o];
#pragma unroll
        for (int k = 0; k < 32; k++) s += tmp1[b * 33 + k] * W2[o * 32 + k];
        tmp2[b * 17 + o] = fmaxf(s, 0.0f);
    }
    __syncthreads();
    if (tid < BT) {
        float s = b3[0];
#pragma unroll
        for (int k = 0; k < 16; k++) s += tmp2[tid * 17 + k] * W3[k];
        out[b0 + tid] = s;
    }
}

extern "C" void kernel_launch(void* const* d_in, const int* in_sizes, int n_in,
                              void* d_out, int out_size) {
    const float* x    = (const float*)d_in[0];
    const float* Wih0 = (const float*)d_in[1];
    const float* Whh0 = (const float*)d_in[2];
    const float* bih0 = (const float*)d_in[3];
    const float* bhh0 = (const float*)d_in[4];
    const float* Wih1 = (const float*)d_in[5];
    const float* Whh1 = (const float*)d_in[6];
    const float* bih1 = (const float*)d_in[7];
    const float* bhh1 = (const float*)d_in[8];
    const float* W1   = (const float*)d_in[9];
    const float* b1   = (const float*)d_in[10];
    const float* W2   = (const float*)d_in[11];
    const float* b2   = (const float*)d_in[12];
    const float* W3   = (const float*)d_in[13];
    const float* b3   = (const float*)d_in[14];
    float* out = (float*)d_out;

    int B = in_sizes[0] / TT;
    int grid = B / BT;  // 128

    cudaFuncSetAttribute(lstm_hmma3_kernel,
                         cudaFuncAttributeMaxDynamicSharedMemorySize, SMEM_REQ);
    lstm_hmma3_kernel<<<grid, NTH, SMEM_REQ>>>(
        x, Wih0, Whh0, bih0, bhh0,
        Wih1, Whh1, bih1, bhh1,
        W1, b1, W2, b2, W3, b3, out);
}

// round 13
// speedup vs baseline: 2.0668x; 1.0271x over previous
#include <cuda_runtime.h>
#include <cuda_fp16.h>
#include <cstdint>

#define HD 50
#define BT 32
#define TT 512
#define NTH 448
#define W0S 72
#define W1S 120
#define HCS 120
#define GSS 33

#define O_W0HI 0
#define O_W0LO 29952
#define O_W1HI 59904
#define O_W1LO 109824
#define O_HCHI 159744
#define O_GS   167424
#define O_XB   222336
#define SMEM_REQ 222592

__device__ __forceinline__ float tanhap(float x) {
    float y; asm("tanh.approx.f32 %0, %1;" : "=f"(y) : "f"(x)); return y;
}
__device__ __forceinline__ float sigap(float x) { return 0.5f * tanhap(0.5f * x) + 0.5f; }
__device__ __forceinline__ uint32_t ld32h(const __half* p) { return *(const uint32_t*)p; }
__device__ __forceinline__ void hmma(float* d, uint32_t a0, uint32_t a1, uint32_t a2,
                                     uint32_t a3, uint32_t b0, uint32_t b1) {
    asm volatile("mma.sync.aligned.m16n8k16.row.col.f32.f16.f16.f32 "
        "{%0,%1,%2,%3}, {%4,%5,%6,%7}, {%8,%9}, {%0,%1,%2,%3};"
        : "+f"(d[0]), "+f"(d[1]), "+f"(d[2]), "+f"(d[3])
        : "r"(a0), "r"(a1), "r"(a2), "r"(a3), "r"(b0), "r"(b1));
}
__device__ __forceinline__ void store_D(float* Gs, float (&D)[4][4], int g, int tg, int rb) {
#pragma unroll
    for (int nt = 0; nt < 4; nt++) {
        int col = 8 * nt + 2 * tg;
        int r0 = (rb + g) * GSS, r1 = (rb + g + 8) * GSS;
        Gs[r0 + col] = D[nt][0]; Gs[r0 + col + 1] = D[nt][1];
        Gs[r1 + col] = D[nt][2]; Gs[r1 + col + 1] = D[nt][3];
    }
}

__global__ __launch_bounds__(NTH, 1)
void lstm_hmma4_kernel(const float* __restrict__ x,
                       const float* __restrict__ Wih0, const float* __restrict__ Whh0,
                       const float* __restrict__ bih0, const float* __restrict__ bhh0,
                       const float* __restrict__ Wih1, const float* __restrict__ Whh1,
                       const float* __restrict__ bih1, const float* __restrict__ bhh1,
                       const float* __restrict__ W1, const float* __restrict__ b1,
                       const float* __restrict__ W2, const float* __restrict__ b2,
                       const float* __restrict__ W3, const float* __restrict__ b3,
                       float* __restrict__ out) {
    extern __shared__ char sm[];
    __half* W0hi = (__half*)(sm + O_W0HI);
    __half* W0lo = (__half*)(sm + O_W0LO);
    __half* W1hi = (__half*)(sm + O_W1HI);
    __half* W1lo = (__half*)(sm + O_W1LO);
    __half* HChi = (__half*)(sm + O_HCHI);
    float*  Gs   = (float*)(sm + O_GS);
    float*  xb   = (float*)(sm + O_XB);

    const int tid = threadIdx.x, lane = tid & 31, warp = tid >> 5;
    const int g = lane >> 2, tg = lane & 3;
    const int b0 = blockIdx.x * BT;

    // ---- pack weights fp16 hi/lo (rows r = 4u+j) ----
    for (int i = tid; i < 208 * 64; i += NTH) {
        int r = i >> 6, k = i & 63;
        float v = 0.0f;
        if (r < 200 && k < HD) v = Whh0[(size_t)((r & 3) * HD + (r >> 2)) * HD + k];
        __half hi = __float2half_rn(v);
        W0hi[r * W0S + k] = hi;
        W0lo[r * W0S + k] = __float2half_rn(v - __half2float(hi));
    }
    for (int i = tid; i < 208 * 128; i += NTH) {
        int r = i >> 7, k = i & 127;
        if (k >= W1S) continue;
        float v = 0.0f;
        if (r < 200 && k < 100) {
            int row = (r & 3) * HD + (r >> 2);
            v = (k < HD) ? Wih1[(size_t)row * HD + k] : Whh1[(size_t)row * HD + (k - HD)];
        }
        __half hi = __float2half_rn(v);
        W1hi[r * W1S + k] = hi;
        W1lo[r * W1S + k] = __float2half_rn(v - __half2float(hi));
    }
    for (int i = tid; i < 32 * HCS; i += NTH) HChi[i] = __half(0.f);
    if (tid < 32) xb[tid] = x[(size_t)(b0 + tid) * TT];

    const int u = tid >> 2, bs = tid & 3;
    const bool cellth = (tid < 200);
    float bias0[4], bias1[4], wx[4];
    if (cellth) {
#pragma unroll
        for (int j = 0; j < 4; j++) {
            int r = j * HD + u;
            bias0[j] = bih0[r] + bhh0[r];
            bias1[j] = bih1[r] + bhh1[r];
            wx[j]    = Wih0[r];
        }
    }
    float c0[8] = {0,0,0,0,0,0,0,0}, c1[8] = {0,0,0,0,0,0,0,0};
    __syncthreads();

    // ---- hoist A-hi fragments (time-invariant) ----
    uint32_t A1h[7][4], A0h[4][4];
    if (warp < 13) {
        const __half* w1 = W1hi + (warp * 16 + g) * W1S + 2 * tg;
#pragma unroll
        for (int c = 0; c < 7; c++) {
            int k0 = 16 * c;
            A1h[c][0] = ld32h(w1 + k0);     A1h[c][1] = ld32h(w1 + 8 * W1S + k0);
            A1h[c][2] = ld32h(w1 + k0 + 8); A1h[c][3] = ld32h(w1 + 8 * W1S + k0 + 8);
        }
        const __half* w0 = W0hi + (warp * 16 + g) * W0S + 2 * tg;
#pragma unroll
        for (int c = 0; c < 4; c++) {
            int k0 = 16 * c;
            A0h[c][0] = ld32h(w0 + k0);     A0h[c][1] = ld32h(w0 + 8 * W0S + k0);
            A0h[c][2] = ld32h(w0 + k0 + 8); A0h[c][3] = ld32h(w0 + 8 * W0S + k0 + 8);
        }
    }
    const __half* hB  = HChi + g * HCS + 2 * tg;
    const __half* w1l = W1lo + (warp * 16 + g) * W1S + 2 * tg;
    const __half* w0l = W0lo + (warp * 16 + g) * W0S + 2 * tg;

    // ---- prologue: epi-0 for t=0 (h(-1)=0 -> gates are bias + wx*x(0)) ----
    if (cellth) {
#pragma unroll
        for (int i = 0; i < 8; i++) {
            int b = bs + 4 * i;
            float xv = xb[b];
            float cv = sigap(bias0[0] + wx[0] * xv) * tanhap(bias0[2] + wx[2] * xv);
            c0[i] = cv;
            HChi[b * HCS + u] =
                __float2half_rn(sigap(bias0[3] + wx[3] * xv) * tanhap(cv));
        }
    }
    __syncthreads();

    // ---- main loop: one fused MMA phase + one fused epilogue per step ----
    for (int t = 0; t < TT; t++) {
        if (warp < 13) {
            float D1[4][4] = {}, D0[4][4] = {};
#pragma unroll
            for (int c = 0; c < 7; c++) {
                int k0 = 16 * c;
                uint32_t l10 = ld32h(w1l + k0),     l11 = ld32h(w1l + 8 * W1S + k0);
                uint32_t l12 = ld32h(w1l + k0 + 8), l13 = ld32h(w1l + 8 * W1S + k0 + 8);
                uint32_t l00 = 0, l01 = 0, l02 = 0, l03 = 0;
                if (c < 4) {
                    l00 = ld32h(w0l + k0);     l01 = ld32h(w0l + 8 * W0S + k0);
                    l02 = ld32h(w0l + k0 + 8); l03 = ld32h(w0l + 8 * W0S + k0 + 8);
                }
#pragma unroll
                for (int nt = 0; nt < 4; nt++) {
                    uint32_t b0f = ld32h(hB + nt * 8 * HCS + k0);
                    uint32_t b1f = ld32h(hB + nt * 8 * HCS + k0 + 8);
                    hmma(D1[nt], A1h[c][0], A1h[c][1], A1h[c][2], A1h[c][3], b0f, b1f);
                    hmma(D1[nt], l10, l11, l12, l13, b0f, b1f);
                    if (c < 4) {
                        hmma(D0[nt], A0h[c][0], A0h[c][1], A0h[c][2], A0h[c][3], b0f, b1f);
                        hmma(D0[nt], l00, l01, l02, l03, b0f, b1f);
                    }
                }
            }
            store_D(Gs, D1, g, tg, warp * 16);
            if (t + 1 < TT) store_D(Gs, D0, g, tg, 208 + warp * 16);
        } else if (t + 1 < TT) {
            xb[((t + 1) & 1) * 32 + lane] = x[(size_t)(b0 + lane) * TT + (t + 1)];
        }
        __syncthreads();

        if (cellth) {
            const float* xr = xb + ((t + 1) & 1) * 32;
#pragma unroll
            for (int i = 0; i < 8; i++) {
                int b = bs + 4 * i;
                // layer-1 update for step t
                float gi = Gs[(4 * u + 0) * GSS + b] + bias1[0];
                float gf = Gs[(4 * u + 1) * GSS + b] + bias1[1];
                float gg = Gs[(4 * u + 2) * GSS + b] + bias1[2];
                float go = Gs[(4 * u + 3) * GSS + b] + bias1[3];
                float cv = sigap(gf) * c1[i] + sigap(gi) * tanhap(gg);
                c1[i] = cv;
                HChi[b * HCS + HD + u] = __float2half_rn(sigap(go) * tanhap(cv));
                if (t + 1 < TT) {
                    // layer-0 update for step t+1
                    float xv = xr[b];
                    float hi0 = Gs[(208 + 4 * u + 0) * GSS + b] + bias0[0] + wx[0] * xv;
                    float hf0 = Gs[(208 + 4 * u + 1) * GSS + b] + bias0[1] + wx[1] * xv;
                    float hg0 = Gs[(208 + 4 * u + 2) * GSS + b] + bias0[2] + wx[2] * xv;
                    float ho0 = Gs[(208 + 4 * u + 3) * GSS + b] + bias0[3] + wx[3] * xv;
                    float cv0 = sigap(hf0) * c0[i] + sigap(hi0) * tanhap(hg0);
                    c0[i] = cv0;
                    HChi[b * HCS + u] = __float2half_rn(sigap(ho0) * tanhap(cv0));
                }
            }
        }
        __syncthreads();
    }

    // ---- MLP head on h1(511) = HC cols 50..99 ----
    float* tmp1 = Gs;
    float* tmp2 = Gs + 1100;
    for (int item = tid; item < BT * 32; item += NTH) {
        int b = item >> 5, o = item & 31;
        float s = b1[o];
#pragma unroll 1
        for (int k = 0; k < HD; k++)
            s += __half2float(HChi[b * HCS + HD + k]) * W1[o * HD + k];
        tmp1[b * 33 + o] = fmaxf(s, 0.0f);
    }
    __syncthreads();
    for (int item = tid; item < BT * 16; item += NTH) {
        int b = item >> 4, o = item & 15;
        float s = b2[o];
#pragma unroll
        for (int k = 0; k < 32; k++) s += tmp1[b * 33 + k] * W2[o * 32 + k];
        tmp2[b * 17 + o] = fmaxf(s, 0.0f);
    }
    __syncthreads();
    if (tid < BT) {
        float s = b3[0];
#pragma unroll
        for (int k = 0; k < 16; k++) s += tmp2[tid * 17 + k] * W3[k];
        out[b0 + tid] = s;
    }
}

extern "C" void kernel_launch(void* const* d_in, const int* in_sizes, int n_in,
                              void* d_out, int out_size) {
    const float* x    = (const float*)d_in[0];
    const float* Wih0 = (const float*)d_in[1];
    const float* Whh0 = (const float*)d_in[2];
    const float* bih0 = (const float*)d_in[3];
    const float* bhh0 = (const float*)d_in[4];
    const float* Wih1 = (const float*)d_in[5];
    const float* Whh1 = (const float*)d_in[6];
    const float* bih1 = (const float*)d_in[7];
    const float* bhh1 = (const float*)d_in[8];
    const float* W1   = (const float*)d_in[9];
    const float* b1   = (const float*)d_in[10];
    const float* W2   = (const float*)d_in[11];
    const float* b2   = (const float*)d_in[12];
    const float* W3   = (const float*)d_in[13];
    const float* b3   = (const float*)d_in[14];
    float* out = (float*)d_out;

    int B = in_sizes[0] / TT;
    int grid = B / BT;  // 128

    cudaFuncSetAttribute(lstm_hmma4_kernel,
                         cudaFuncAttributeMaxDynamicSharedMemorySize, SMEM_REQ);
    lstm_hmma4_kernel<<<grid, NTH, SMEM_REQ>>>(
        x, Wih0, Whh0, bih0, bhh0,
        Wih1, Whh1, bih1, bhh1,
        W1, b1, W2, b2, W3, b3, out);
}

// round 14
// speedup vs baseline: 2.1404x; 1.0356x over previous
#include <cuda_runtime.h>
#include <cuda_fp16.h>
#include <cstdint>

#define HD 50
#define BT 32
#define TT 512
#define NTH 448
#define W0S 72
#define W1S 120
#define HCS 120
#define GSS 33

#define O_W0HI 0
#define O_W0LO 29952
#define O_W1HI 59904
#define O_W1LO 109824
#define O_HCHI 159744
#define O_GS   167424
#define O_XB   222336
#define SMEM_REQ 222592

__device__ __forceinline__ float tanhap(float x) {
    float y; asm("tanh.approx.f32 %0, %1;" : "=f"(y) : "f"(x)); return y;
}
__device__ __forceinline__ float sigap(float x) { return 0.5f * tanhap(0.5f * x) + 0.5f; }
__device__ __forceinline__ uint32_t ld32h(const __half* p) { return *(const uint32_t*)p; }
__device__ __forceinline__ void hmma(float* d, uint32_t a0, uint32_t a1, uint32_t a2,
                                     uint32_t a3, uint32_t b0, uint32_t b1) {
    asm volatile("mma.sync.aligned.m16n8k16.row.col.f32.f16.f16.f32 "
        "{%0,%1,%2,%3}, {%4,%5,%6,%7}, {%8,%9}, {%0,%1,%2,%3};"
        : "+f"(d[0]), "+f"(d[1]), "+f"(d[2]), "+f"(d[3])
        : "r"(a0), "r"(a1), "r"(a2), "r"(a3), "r"(b0), "r"(b1));
}
__device__ __forceinline__ void store_D(float* Gs, float (&D)[4][4], int g, int tg, int rb) {
#pragma unroll
    for (int nt = 0; nt < 4; nt++) {
        int col = 8 * nt + 2 * tg;
        int r0 = (rb + g) * GSS, r1 = (rb + g + 8) * GSS;
        Gs[r0 + col] = D[nt][0]; Gs[r0 + col + 1] = D[nt][1];
        Gs[r1 + col] = D[nt][2]; Gs[r1 + col + 1] = D[nt][3];
    }
}

__global__ __launch_bounds__(NTH, 1)
void lstm_hmma5_kernel(const float* __restrict__ x,
                       const float* __restrict__ Wih0, const float* __restrict__ Whh0,
                       const float* __restrict__ bih0, const float* __restrict__ bhh0,
                       const float* __restrict__ Wih1, const float* __restrict__ Whh1,
                       const float* __restrict__ bih1, const float* __restrict__ bhh1,
                       const float* __restrict__ W1, const float* __restrict__ b1,
                       const float* __restrict__ W2, const float* __restrict__ b2,
                       const float* __restrict__ W3, const float* __restrict__ b3,
                       float* __restrict__ out) {
    extern __shared__ char sm[];
    __half* W0hi = (__half*)(sm + O_W0HI);
    __half* W0lo = (__half*)(sm + O_W0LO);
    __half* W1hi = (__half*)(sm + O_W1HI);
    __half* W1lo = (__half*)(sm + O_W1LO);
    __half* HChi = (__half*)(sm + O_HCHI);
    float*  Gs   = (float*)(sm + O_GS);
    float*  xb   = (float*)(sm + O_XB);

    const int tid = threadIdx.x, lane = tid & 31, warp = tid >> 5;
    const int g = lane >> 2, tg = lane & 3;
    const int b0 = blockIdx.x * BT;

    // ---- pack weights fp16 hi/lo (rows r = 4u+j) ----
    for (int i = tid; i < 208 * 64; i += NTH) {
        int r = i >> 6, k = i & 63;
        float v = 0.0f;
        if (r < 200 && k < HD) v = Whh0[(size_t)((r & 3) * HD + (r >> 2)) * HD + k];
        __half hi = __float2half_rn(v);
        W0hi[r * W0S + k] = hi;
        W0lo[r * W0S + k] = __float2half_rn(v - __half2float(hi));
    }
    for (int i = tid; i < 208 * 128; i += NTH) {
        int r = i >> 7, k = i & 127;
        if (k >= W1S) continue;
        float v = 0.0f;
        if (r < 200 && k < 100) {
            int row = (r & 3) * HD + (r >> 2);
            v = (k < HD) ? Wih1[(size_t)row * HD + k] : Whh1[(size_t)row * HD + (k - HD)];
        }
        __half hi = __float2half_rn(v);
        W1hi[r * W1S + k] = hi;
        W1lo[r * W1S + k] = __float2half_rn(v - __half2float(hi));
    }
    for (int i = tid; i < 32 * HCS; i += NTH) HChi[i] = __half(0.f);
    if (tid < 32) xb[tid] = x[(size_t)(b0 + tid) * TT];

    // ---- epilogue groups: L1 cells tid 0..199, L0 cells tid 208..407 ----
    const bool cel1 = (tid < 200);
    const bool cel0 = (tid >= 208 && tid < 408);
    const int u1 = tid >> 2,          bs1 = tid & 3;
    const int u0 = (tid - 208) >> 2,  bs0 = (tid - 208) & 3;
    float bias1[4], bias0[4], wx[4];
    if (cel1) {
#pragma unroll
        for (int j = 0; j < 4; j++) { int r = j * HD + u1; bias1[j] = bih1[r] + bhh1[r]; }
    }
    if (cel0) {
#pragma unroll
        for (int j = 0; j < 4; j++) {
            int r = j * HD + u0;
            bias0[j] = bih0[r] + bhh0[r];
            wx[j]    = Wih0[r];
        }
    }
    float cst[8] = {0,0,0,0,0,0,0,0};    // c1 for group-1, c0 for group-0
    __syncthreads();

    // ---- hoist layer-1 A-hi fragments (time-invariant) ----
    uint32_t A1h[7][4];
    if (warp < 13) {
        const __half* w1 = W1hi + (warp * 16 + g) * W1S + 2 * tg;
#pragma unroll
        for (int c = 0; c < 7; c++) {
            int k0 = 16 * c;
            A1h[c][0] = ld32h(w1 + k0);     A1h[c][1] = ld32h(w1 + 8 * W1S + k0);
            A1h[c][2] = ld32h(w1 + k0 + 8); A1h[c][3] = ld32h(w1 + 8 * W1S + k0 + 8);
        }
    }
    const __half* hB  = HChi + g * HCS + 2 * tg;
    const __half* w1l = W1lo + (warp * 16 + g) * W1S + 2 * tg;
    const __half* w0h = W0hi + (warp * 16 + g) * W0S + 2 * tg;
    const __half* w0l = W0lo + (warp * 16 + g) * W0S + 2 * tg;

    // ---- prologue: epi-0 for t=0 (h(-1)=0) ----
    if (cel0) {
#pragma unroll
        for (int i = 0; i < 8; i++) {
            int b = bs0 + 4 * i;
            float xv = xb[b];
            float cv = sigap(bias0[0] + wx[0] * xv) * tanhap(bias0[2] + wx[2] * xv);
            cst[i] = cv;
            HChi[b * HCS + u0] =
                __float2half_rn(sigap(bias0[3] + wx[3] * xv) * tanhap(cv));
        }
    }
    __syncthreads();

    for (int t = 0; t < TT; t++) {
        if (warp < 13) {
            float D1[4][4] = {}, D0[4][4] = {};
            uint32_t Bf[8];
#pragma unroll
            for (int nt = 0; nt < 4; nt++) {
                Bf[2 * nt]     = ld32h(hB + nt * 8 * HCS);
                Bf[2 * nt + 1] = ld32h(hB + nt * 8 * HCS + 8);
            }
#pragma unroll
            for (int c = 0; c < 7; c++) {
                int k0 = 16 * c;
                uint32_t Bn[8];
                if (c < 6) {
#pragma unroll
                    for (int nt = 0; nt < 4; nt++) {
                        Bn[2 * nt]     = ld32h(hB + nt * 8 * HCS + k0 + 16);
                        Bn[2 * nt + 1] = ld32h(hB + nt * 8 * HCS + k0 + 24);
                    }
                }
                uint32_t l10 = ld32h(w1l + k0),     l11 = ld32h(w1l + 8 * W1S + k0);
                uint32_t l12 = ld32h(w1l + k0 + 8), l13 = ld32h(w1l + 8 * W1S + k0 + 8);
                uint32_t h00 = 0, h01 = 0, h02 = 0, h03 = 0;
                uint32_t l00 = 0, l01 = 0, l02 = 0, l03 = 0;
                if (c < 4) {
                    h00 = ld32h(w0h + k0);     h01 = ld32h(w0h + 8 * W0S + k0);
                    h02 = ld32h(w0h + k0 + 8); h03 = ld32h(w0h + 8 * W0S + k0 + 8);
                    l00 = ld32h(w0l + k0);     l01 = ld32h(w0l + 8 * W0S + k0);
                    l02 = ld32h(w0l + k0 + 8); l03 = ld32h(w0l + 8 * W0S + k0 + 8);
                }
#pragma unroll
                for (int nt = 0; nt < 4; nt++) {
                    uint32_t b0f = Bf[2 * nt], b1f = Bf[2 * nt + 1];
                    hmma(D1[nt], A1h[c][0], A1h[c][1], A1h[c][2], A1h[c][3], b0f, b1f);
                    hmma(D1[nt], l10, l11, l12, l13, b0f, b1f);
                    if (c < 4) {
                        hmma(D0[nt], h00, h01, h02, h03, b0f, b1f);
                        hmma(D0[nt], l00, l01, l02, l03, b0f, b1f);
                    }
                }
                if (c < 6) {
#pragma unroll
                    for (int q = 0; q < 8; q++) Bf[q] = Bn[q];
                }
            }
            store_D(Gs, D1, g, tg, warp * 16);
            if (t + 1 < TT) store_D(Gs, D0, g, tg, 208 + warp * 16);
        } else if (t + 1 < TT) {
            xb[((t + 1) & 1) * 32 + lane] = x[(size_t)(b0 + lane) * TT + (t + 1)];
        }
        __syncthreads();

        if (cel1) {
#pragma unroll
            for (int i = 0; i < 8; i++) {
                int b = bs1 + 4 * i;
                float gi = Gs[(4 * u1 + 0) * GSS + b] + bias1[0];
                float gf = Gs[(4 * u1 + 1) * GSS + b] + bias1[1];
                float gg = Gs[(4 * u1 + 2) * GSS + b] + bias1[2];
                float go = Gs[(4 * u1 + 3) * GSS + b] + bias1[3];
                float cv = sigap(gf) * cst[i] + sigap(gi) * tanhap(gg);
                cst[i] = cv;
                HChi[b * HCS + HD + u1] = __float2half_rn(sigap(go) * tanhap(cv));
            }
        } else if (cel0 && t + 1 < TT) {
            const float* xr = xb + ((t + 1) & 1) * 32;
#pragma unroll
            for (int i = 0; i < 8; i++) {
                int b = bs0 + 4 * i;
                float xv = xr[b];
                float gi = Gs[(208 + 4 * u0 + 0) * GSS + b] + bias0[0] + wx[0] * xv;
                float gf = Gs[(208 + 4 * u0 + 1) * GSS + b] + bias0[1] + wx[1] * xv;
                float gg = Gs[(208 + 4 * u0 + 2) * GSS + b] + bias0[2] + wx[2] * xv;
                float go = Gs[(208 + 4 * u0 + 3) * GSS + b] + bias0[3] + wx[3] * xv;
                float cv = sigap(gf) * cst[i] + sigap(gi) * tanhap(gg);
                cst[i] = cv;
                HChi[b * HCS + u0] = __float2half_rn(sigap(go) * tanhap(cv));
            }
        }
        __syncthreads();
    }

    // ---- MLP head on h1(511) = HC cols 50..99 ----
    float* tmp1 = Gs;
    float* tmp2 = Gs + 1100;
    for (int item = tid; item < BT * 32; item += NTH) {
        int b = item >> 5, o = item & 31;
        float s = b1[o];
#pragma unroll 1
        for (int k = 0; k < HD; k++)
            s += __half2float(HChi[b * HCS + HD + k]) * W1[o * HD + k];
        tmp1[b * 33 + o] = fmaxf(s, 0.0f);
    }
    __syncthreads();
    for (int item = tid; item < BT * 16; item += NTH) {
        int b = item >> 4, o = item & 15;
        float s = b2[o];
#pragma unroll
        for (int k = 0; k < 32; k++) s += tmp1[b * 33 + k] * W2[o * 32 + k];
        tmp2[b * 17 + o] = fmaxf(s, 0.0f);
    }
    __syncthreads();
    if (tid < BT) {
        float s = b3[0];
#pragma unroll
        for (int k = 0; k < 16; k++) s += tmp2[tid * 17 + k] * W3[k];
        out[b0 + tid] = s;
    }
}

extern "C" void kernel_launch(void* const* d_in, const int* in_sizes, int n_in,
                              void* d_out, int out_size) {
    const float* x    = (const float*)d_in[0];
    const float* Wih0 = (const float*)d_in[1];
    const float* Whh0 = (const float*)d_in[2];
    const float* bih0 = (const float*)d_in[3];
    const float* bhh0 = (const float*)d_in[4];
    const float* Wih1 = (const float*)d_in[5];
    const float* Whh1 = (const float*)d_in[6];
    const float* bih1 = (const float*)d_in[7];
    const float* bhh1 = (const float*)d_in[8];
    const float* W1   = (const float*)d_in[9];
    const float* b1   = (const float*)d_in[10];
    const float* W2   = (const float*)d_in[11];
    const float* b2   = (const float*)d_in[12];
    const float* W3   = (const float*)d_in[13];
    const float* b3   = (const float*)d_in[14];
    float* out = (float*)d_out;

    int B = in_sizes[0] / TT;
    int grid = B / BT;  // 128

    cudaFuncSetAttribute(lstm_hmma5_kernel,
                         cudaFuncAttributeMaxDynamicSharedMemorySize, SMEM_REQ);
    lstm_hmma5_kernel<<<grid, NTH, SMEM_REQ>>>(
        x, Wih0, Whh0, bih0, bhh0,
        Wih1, Whh1, bih1, bhh1,
        W1, b1, W2, b2, W3, b3, out);
}

// round 15
// speedup vs baseline: 2.6550x; 1.2404x over previous
#include <cuda_runtime.h>
#include <cuda_fp16.h>
#include <cstdint>

#define HD 50
#define BT 32
#define TT 512
#define NTH 448
#define W0S 72
#define W1S 120
#define HCS 120

#define O_W0HI 0
#define O_W0LO 29952
#define O_W1HI 59904
#define O_W1LO 109824
#define O_HC   159744          // 2 slots x 32 x 120 halves (7680 B each)
#define O_XB   175104          // 2 x 32 f32
#define SMEM_REQ 175360

__device__ __forceinline__ float tanhap(float x) {
    float y; asm("tanh.approx.f32 %0, %1;" : "=f"(y) : "f"(x)); return y;
}
__device__ __forceinline__ float sigap(float x) { return 0.5f * tanhap(0.5f * x) + 0.5f; }
__device__ __forceinline__ uint32_t ld32h(const __half* p) { return *(const uint32_t*)p; }
__device__ __forceinline__ void hmma(float* d, uint32_t a0, uint32_t a1, uint32_t a2,
                                     uint32_t a3, uint32_t b0, uint32_t b1) {
    asm volatile("mma.sync.aligned.m16n8k16.row.col.f32.f16.f16.f32 "
        "{%0,%1,%2,%3}, {%4,%5,%6,%7}, {%8,%9}, {%0,%1,%2,%3};"
        : "+f"(d[0]), "+f"(d[1]), "+f"(d[2]), "+f"(d[3])
        : "r"(a0), "r"(a1), "r"(a2), "r"(a3), "r"(b0), "r"(b1));
}

// 4x4 transpose across the 4 gate-lanes (lane bits 2,3): D[nt][k] -> T[k][gate]
__device__ __forceinline__ void epi_tr(float (&D)[4][4], float (&T)[4][4], int j) {
    const bool hi2 = j & 2, hi1 = j & 1;
#pragma unroll
    for (int k = 0; k < 4; k++) {
        float e0 = D[0][k], e1 = D[1][k], e2 = D[2][k], e3 = D[3][k];
        float s0 = hi2 ? e0 : e2, s1 = hi2 ? e1 : e3;
        float r0 = __shfl_xor_sync(0xffffffffu, s0, 8);
        float r1 = __shfl_xor_sync(0xffffffffu, s1, 8);
        e0 = hi2 ? r0 : e0; e1 = hi2 ? r1 : e1;
        e2 = hi2 ? e2 : r0; e3 = hi2 ? e3 : r1;
        float t0 = hi1 ? e0 : e1, t1 = hi1 ? e2 : e3;
        float q0 = __shfl_xor_sync(0xffffffffu, t0, 4);
        float q1 = __shfl_xor_sync(0xffffffffu, t1, 4);
        e0 = hi1 ? q0 : e0; e1 = hi1 ? e1 : q0;
        e2 = hi1 ? q1 : e2; e3 = hi1 ? e3 : q1;
        T[k][0] = e0; T[k][1] = e1; T[k][2] = e2; T[k][3] = e3;
    }
}

// cell chain for this lane's 4 cells; writes h fp16 into HCw at column base colu
__device__ __forceinline__ void epi_cell(float (&T)[4][4], float* cst, __half* HCw,
                                         int colu, int j, int tg, int ubase) {
#pragma unroll
    for (int h = 0; h < 2; h++) {
        int u = ubase + 2 * h;
#pragma unroll
        for (int k1 = 0; k1 < 2; k1++) {
            int k = 2 * h + k1;
            float i_ = sigap(T[k][0]), f_ = sigap(T[k][1]);
            float g_ = tanhap(T[k][2]), o_ = sigap(T[k][3]);
            float cv = f_ * cst[2 * h + k1] + i_ * g_;
            cst[2 * h + k1] = cv;
            if (u < HD) {
                int col = 8 * j + 2 * tg + k1;
                HCw[col * HCS + colu + u] = __float2half_rn(o_ * tanhap(cv));
            }
        }
    }
}

__global__ __launch_bounds__(NTH, 1)
void lstm_hmma6_kernel(const float* __restrict__ x,
                       const float* __restrict__ Wih0, const float* __restrict__ Whh0,
                       const float* __restrict__ bih0, const float* __restrict__ bhh0,
                       const float* __restrict__ Wih1, const float* __restrict__ Whh1,
                       const float* __restrict__ bih1, const float* __restrict__ bhh1,
                       const float* __restrict__ W1, const float* __restrict__ b1,
                       const float* __restrict__ W2, const float* __restrict__ b2,
                       const float* __restrict__ W3, const float* __restrict__ b3,
                       float* __restrict__ out) {
    extern __shared__ char sm[];
    __half* W0hi = (__half*)(sm + O_W0HI);
    __half* W0lo = (__half*)(sm + O_W0LO);
    __half* W1hi = (__half*)(sm + O_W1HI);
    __half* W1lo = (__half*)(sm + O_W1LO);
    __half* HC   = (__half*)(sm + O_HC);     // 2 slots of 3840 halves
    float*  xb   = (float*)(sm + O_XB);

    const int tid = threadIdx.x, lane = tid & 31, warp = tid >> 5;
    const int g = lane >> 2, tg = lane & 3;
    const int j = g & 3, a = g >> 2;
    const int b0 = blockIdx.x * BT;

    // ---- pack weights fp16 hi/lo (rows r = 4u+j) ----
    for (int i = tid; i < 208 * 64; i += NTH) {
        int r = i >> 6, k = i & 63;
        float v = 0.0f;
        if (r < 200 && k < HD) v = Whh0[(size_t)((r & 3) * HD + (r >> 2)) * HD + k];
        __half hi = __float2half_rn(v);
        W0hi[r * W0S + k] = hi;
        W0lo[r * W0S + k] = __float2half_rn(v - __half2float(hi));
    }
    for (int i = tid; i < 208 * 128; i += NTH) {
        int r = i >> 7, k = i & 127;
        if (k >= W1S) continue;
        float v = 0.0f;
        if (r < 200 && k < 100) {
            int row = (r & 3) * HD + (r >> 2);
            v = (k < HD) ? Wih1[(size_t)row * HD + k] : Whh1[(size_t)row * HD + (k - HD)];
        }
        __half hi = __float2half_rn(v);
        W1hi[r * W1S + k] = hi;
        W1lo[r * W1S + k] = __float2half_rn(v - __half2float(hi));
    }
    for (int i = tid; i < 2 * 32 * HCS; i += NTH) HC[i] = __half(0.f);
    if (tid < 32) xb[tid] = x[(size_t)(b0 + tid) * TT];
    else if (tid < 64) xb[32 + (tid - 32)] = x[(size_t)(b0 + tid - 32) * TT + 1];

    // per-lane own-gate constants (gate j, units ubase, ubase+2)
    const int ubase = 4 * warp + a;
    float b1own[2] = {0.f, 0.f}, b0own[2] = {0.f, 0.f}, wxo[2] = {0.f, 0.f};
    if (warp < 13) {
#pragma unroll
        for (int h = 0; h < 2; h++) {
            int u = ubase + 2 * h;
            if (u < HD) {
                int r = j * HD + u;
                b1own[h] = bih1[r] + bhh1[r];
                b0own[h] = bih0[r] + bhh0[r];
                wxo[h]   = Wih0[r];
            }
        }
    }
    float c1[4] = {0.f, 0.f, 0.f, 0.f}, c0[4] = {0.f, 0.f, 0.f, 0.f};
    __syncthreads();

    // ---- hoist layer-1 A-hi fragments ----
    uint32_t A1h[7][4];
    if (warp < 13) {
        const __half* w1 = W1hi + (warp * 16 + g) * W1S + 2 * tg;
#pragma unroll
        for (int c = 0; c < 7; c++) {
            int k0 = 16 * c;
            A1h[c][0] = ld32h(w1 + k0);     A1h[c][1] = ld32h(w1 + 8 * W1S + k0);
            A1h[c][2] = ld32h(w1 + k0 + 8); A1h[c][3] = ld32h(w1 + 8 * W1S + k0 + 8);
        }
    }
    const __half* w1l = W1lo + (warp * 16 + g) * W1S + 2 * tg;
    const __half* w0h = W0hi + (warp * 16 + g) * W0S + 2 * tg;
    const __half* w0l = W0lo + (warp * 16 + g) * W0S + 2 * tg;

    // ---- prologue: layer-0 cell update for t=0 (h(-1)=0) -> h0(0) into slot 0 ----
    if (warp < 13) {
        float D0[4][4], T[4][4];
#pragma unroll
        for (int nt = 0; nt < 4; nt++) {
            float2 xv = *(const float2*)(xb + 8 * nt + 2 * tg);
#pragma unroll
            for (int k = 0; k < 4; k++)
                D0[nt][k] = b0own[k >> 1] + wxo[k >> 1] * ((k & 1) ? xv.y : xv.x);
        }
        epi_tr(D0, T, j);
        epi_cell(T, c0, HC, 0, j, tg, ubase);
    }
    __syncthreads();

    for (int t = 0; t < TT; t++) {
        const __half* HCr = HC + (t & 1) * 32 * HCS;
        __half* HCw = HC + ((t + 1) & 1) * 32 * HCS;
        if (warp < 13) {
            const __half* hB = HCr + g * HCS + 2 * tg;
            float D1[4][4] = {}, D0[4][4] = {};
            uint32_t Bf[8];
#pragma unroll
            for (int nt = 0; nt < 4; nt++) {
                Bf[2 * nt]     = ld32h(hB + nt * 8 * HCS);
                Bf[2 * nt + 1] = ld32h(hB + nt * 8 * HCS + 8);
            }
#pragma unroll
            for (int c = 0; c < 7; c++) {
                int k0 = 16 * c;
                uint32_t Bn[8];
                if (c < 6) {
#pragma unroll
                    for (int nt = 0; nt < 4; nt++) {
                        Bn[2 * nt]     = ld32h(hB + nt * 8 * HCS + k0 + 16);
                        Bn[2 * nt + 1] = ld32h(hB + nt * 8 * HCS + k0 + 24);
                    }
                }
                uint32_t l10 = ld32h(w1l + k0),     l11 = ld32h(w1l + 8 * W1S + k0);
                uint32_t l12 = ld32h(w1l + k0 + 8), l13 = ld32h(w1l + 8 * W1S + k0 + 8);
                uint32_t h00 = 0, h01 = 0, h02 = 0, h03 = 0;
                uint32_t l00 = 0, l01 = 0, l02 = 0, l03 = 0;
                if (c < 4) {
                    h00 = ld32h(w0h + k0);     h01 = ld32h(w0h + 8 * W0S + k0);
                    h02 = ld32h(w0h + k0 + 8); h03 = ld32h(w0h + 8 * W0S + k0 + 8);
                    l00 = ld32h(w0l + k0);     l01 = ld32h(w0l + 8 * W0S + k0);
                    l02 = ld32h(w0l + k0 + 8); l03 = ld32h(w0l + 8 * W0S + k0 + 8);
                }
#pragma unroll
                for (int nt = 0; nt < 4; nt++) {
                    uint32_t b0f = Bf[2 * nt], b1f = Bf[2 * nt + 1];
                    hmma(D1[nt], A1h[c][0], A1h[c][1], A1h[c][2], A1h[c][3], b0f, b1f);
                    hmma(D1[nt], l10, l11, l12, l13, b0f, b1f);
                    if (c < 4) {
                        hmma(D0[nt], h00, h01, h02, h03, b0f, b1f);
                        hmma(D0[nt], l00, l01, l02, l03, b0f, b1f);
                    }
                }
                if (c < 6) {
#pragma unroll
                    for (int q = 0; q < 8; q++) Bf[q] = Bn[q];
                }
            }
            // ---- in-register epilogue ----
            float T[4][4];
#pragma unroll
            for (int nt = 0; nt < 4; nt++)
#pragma unroll
                for (int k = 0; k < 4; k++) D1[nt][k] += b1own[k >> 1];
            epi_tr(D1, T, j);
            epi_cell(T, c1, HCw, HD, j, tg, ubase);
            if (t + 1 < TT) {
                const float* xr = xb + ((t + 1) & 1) * 32;
#pragma unroll
                for (int nt = 0; nt < 4; nt++) {
                    float2 xv = *(const float2*)(xr + 8 * nt + 2 * tg);
#pragma unroll
                    for (int k = 0; k < 4; k++)
                        D0[nt][k] += b0own[k >> 1] + wxo[k >> 1] * ((k & 1) ? xv.y : xv.x);
                }
                epi_tr(D0, T, j);
                epi_cell(T, c0, HCw, 0, j, tg, ubase);
            }
        } else {
            if (t + 2 < TT)
                xb[(t & 1) * 32 + lane] = x[(size_t)(b0 + lane) * TT + (t + 2)];
        }
        __syncthreads();
    }

    // ---- MLP head on h1(511) = HC slot 0, cols 50..99 ----
    float* tmp1 = (float*)sm;            // weights dead; reuse as scratch
    float* tmp2 = tmp1 + 1100;
    for (int item = tid; item < BT * 32; item += NTH) {
        int b = item >> 5, o = item & 31;
        float s = b1[o];
#pragma unroll 1
        for (int k = 0; k < HD; k++)
            s += __half2float(HC[b * HCS + HD + k]) * W1[o * HD + k];
        tmp1[b * 33 + o] = fmaxf(s, 0.0f);
    }
    __syncthreads();
    for (int item = tid; item < BT * 16; item += NTH) {
        int b = item >> 4, o = item & 15;
        float s = b2[o];
#pragma unroll
        for (int k = 0; k < 32; k++) s += tmp1[b * 33 + k] * W2[o * 32 + k];
        tmp2[b * 17 + o] = fmaxf(s, 0.0f);
    }
    __syncthreads();
    if (tid < BT) {
        float s = b3[0];
#pragma unroll
        for (int k = 0; k < 16; k++) s += tmp2[tid * 17 + k] * W3[k];
        out[b0 + tid] = s;
    }
}

extern "C" void kernel_launch(void* const* d_in, const int* in_sizes, int n_in,
                              void* d_out, int out_size) {
    const float* x    = (const float*)d_in[0];
    const float* Wih0 = (const float*)d_in[1];
    const float* Whh0 = (const float*)d_in[2];
    const float* bih0 = (const float*)d_in[3];
    const float* bhh0 = (const float*)d_in[4];
    const float* Wih1 = (const float*)d_in[5];
    const float* Whh1 = (const float*)d_in[6];
    const float* bih1 = (const float*)d_in[7];
    const float* bhh1 = (const float*)d_in[8];
    const float* W1   = (const float*)d_in[9];
    const float* b1   = (const float*)d_in[10];
    const float* W2   = (const float*)d_in[11];
    const float* b2   = (const float*)d_in[12];
    const float* W3   = (const float*)d_in[13];
    const float* b3   = (const float*)d_in[14];
    float* out = (float*)d_out;

    int B = in_sizes[0] / TT;
    int grid = B / BT;  // 128

    cudaFuncSetAttribute(lstm_hmma6_kernel,
                         cudaFuncAttributeMaxDynamicSharedMemorySize, SMEM_REQ);
    lstm_hmma6_kernel<<<grid, NTH, SMEM_REQ>>>(
        x, Wih0, Whh0, bih0, bhh0,
        Wih1, Whh1, bih1, bhh1,
        W1, b1, W2, b2, W3, b3, out);
}

// round 16
// speedup vs baseline: 3.1078x; 1.1705x over previous
#include <cuda_runtime.h>
#include <cuda_fp16.h>
#include <cstdint>

#define HD 50
#define BT 32
#define TT 512
#define NTH 448
#define W0S 64
#define W1S 120
#define HCS 120

#define O_W0HI 0
#define O_W1HI 26624
#define O_HC   76544           // 2 slots x 32 x 120 halves (7680 B each)
#define O_XB   91904           // 2 x 32 f32
#define SMEM_REQ 92160

__device__ __forceinline__ float tanhap(float x) {
    float y; asm("tanh.approx.f32 %0, %1;" : "=f"(y) : "f"(x)); return y;
}
__device__ __forceinline__ float sigap(float x) { return 0.5f * tanhap(0.5f * x) + 0.5f; }
__device__ __forceinline__ uint32_t ld32h(const __half* p) { return *(const uint32_t*)p; }
__device__ __forceinline__ void hmma(float* d, uint32_t a0, uint32_t a1, uint32_t a2,
                                     uint32_t a3, uint32_t b0, uint32_t b1) {
    asm volatile("mma.sync.aligned.m16n8k16.row.col.f32.f16.f16.f32 "
        "{%0,%1,%2,%3}, {%4,%5,%6,%7}, {%8,%9}, {%0,%1,%2,%3};"
        : "+f"(d[0]), "+f"(d[1]), "+f"(d[2]), "+f"(d[3])
        : "r"(a0), "r"(a1), "r"(a2), "r"(a3), "r"(b0), "r"(b1));
}

// 4x4 transpose across the 4 gate-lanes (lane bits 2,3): D[nt][k] -> T[k][gate]
__device__ __forceinline__ void epi_tr(float (&D)[4][4], float (&T)[4][4], int j) {
    const bool hi2 = j & 2, hi1 = j & 1;
#pragma unroll
    for (int k = 0; k < 4; k++) {
        float e0 = D[0][k], e1 = D[1][k], e2 = D[2][k], e3 = D[3][k];
        float s0 = hi2 ? e0 : e2, s1 = hi2 ? e1 : e3;
        float r0 = __shfl_xor_sync(0xffffffffu, s0, 8);
        float r1 = __shfl_xor_sync(0xffffffffu, s1, 8);
        e0 = hi2 ? r0 : e0; e1 = hi2 ? r1 : e1;
        e2 = hi2 ? e2 : r0; e3 = hi2 ? e3 : r1;
        float t0 = hi1 ? e0 : e1, t1 = hi1 ? e2 : e3;
        float q0 = __shfl_xor_sync(0xffffffffu, t0, 4);
        float q1 = __shfl_xor_sync(0xffffffffu, t1, 4);
        e0 = hi1 ? q0 : e0; e1 = hi1 ? e1 : q0;
        e2 = hi1 ? q1 : e2; e3 = hi1 ? e3 : q1;
        T[k][0] = e0; T[k][1] = e1; T[k][2] = e2; T[k][3] = e3;
    }
}

// cell chain for this lane's 4 cells; writes h fp16 into HCw at column base colu
__device__ __forceinline__ void epi_cell(float (&T)[4][4], float* cst, __half* HCw,
                                         int colu, int j, int tg, int ubase) {
#pragma unroll
    for (int h = 0; h < 2; h++) {
        int u = ubase + 2 * h;
#pragma unroll
        for (int k1 = 0; k1 < 2; k1++) {
            int k = 2 * h + k1;
            float i_ = sigap(T[k][0]), f_ = sigap(T[k][1]);
            float g_ = tanhap(T[k][2]), o_ = sigap(T[k][3]);
            float cv = f_ * cst[2 * h + k1] + i_ * g_;
            cst[2 * h + k1] = cv;
            if (u < HD) {
                int col = 8 * j + 2 * tg + k1;
                HCw[col * HCS + colu + u] = __float2half_rn(o_ * tanhap(cv));
            }
        }
    }
}

__global__ __launch_bounds__(NTH, 1)
void lstm_hmma7_kernel(const float* __restrict__ x,
                       const float* __restrict__ Wih0, const float* __restrict__ Whh0,
                       const float* __restrict__ bih0, const float* __restrict__ bhh0,
                       const float* __restrict__ Wih1, const float* __restrict__ Whh1,
                       const float* __restrict__ bih1, const float* __restrict__ bhh1,
                       const float* __restrict__ W1, const float* __restrict__ b1,
                       const float* __restrict__ W2, const float* __restrict__ b2,
                       const float* __restrict__ W3, const float* __restrict__ b3,
                       float* __restrict__ out) {
    extern __shared__ char sm[];
    __half* W0hi = (__half*)(sm + O_W0HI);
    __half* W1hi = (__half*)(sm + O_W1HI);
    __half* HC   = (__half*)(sm + O_HC);     // 2 slots of 3840 halves
    float*  xb   = (float*)(sm + O_XB);

    const int tid = threadIdx.x, lane = tid & 31, warp = tid >> 5;
    const int g = lane >> 2, tg = lane & 3;
    const int j = g & 3, a = g >> 2;
    const int b0 = blockIdx.x * BT;

    // ---- pack weights fp16 hi (rows r = 4u+j) ----
    for (int i = tid; i < 208 * 64; i += NTH) {
        int r = i >> 6, k = i & 63;
        float v = 0.0f;
        if (r < 200 && k < HD) v = Whh0[(size_t)((r & 3) * HD + (r >> 2)) * HD + k];
        W0hi[r * W0S + k] = __float2half_rn(v);
    }
    for (int i = tid; i < 208 * 128; i += NTH) {
        int r = i >> 7, k = i & 127;
        if (k >= W1S) continue;
        float v = 0.0f;
        if (r < 200 && k < 100) {
            int row = (r & 3) * HD + (r >> 2);
            v = (k < HD) ? Wih1[(size_t)row * HD + k] : Whh1[(size_t)row * HD + (k - HD)];
        }
        W1hi[r * W1S + k] = __float2half_rn(v);
    }
    for (int i = tid; i < 2 * 32 * HCS; i += NTH) HC[i] = __half(0.f);
    if (tid < 32) xb[tid] = x[(size_t)(b0 + tid) * TT];
    else if (tid < 64) xb[32 + (tid - 32)] = x[(size_t)(b0 + tid - 32) * TT + 1];

    // per-lane own-gate constants (gate j, units ubase, ubase+2)
    const int ubase = 4 * warp + a;
    float b1own[2] = {0.f, 0.f}, b0own[2] = {0.f, 0.f}, wxo[2] = {0.f, 0.f};
    if (warp < 13) {
#pragma unroll
        for (int h = 0; h < 2; h++) {
            int u = ubase + 2 * h;
            if (u < HD) {
                int r = j * HD + u;
                b1own[h] = bih1[r] + bhh1[r];
                b0own[h] = bih0[r] + bhh0[r];
                wxo[h]   = Wih0[r];
            }
        }
    }
    float c1[4] = {0.f, 0.f, 0.f, 0.f}, c0[4] = {0.f, 0.f, 0.f, 0.f};
    __syncthreads();

    // ---- hoist layer-1 A-hi fragments ----
    uint32_t A1h[7][4];
    if (warp < 13) {
        const __half* w1 = W1hi + (warp * 16 + g) * W1S + 2 * tg;
#pragma unroll
        for (int c = 0; c < 7; c++) {
            int k0 = 16 * c;
            A1h[c][0] = ld32h(w1 + k0);     A1h[c][1] = ld32h(w1 + 8 * W1S + k0);
            A1h[c][2] = ld32h(w1 + k0 + 8); A1h[c][3] = ld32h(w1 + 8 * W1S + k0 + 8);
        }
    }
    const __half* w0h = W0hi + (warp * 16 + g) * W0S + 2 * tg;

    // ---- prologue: layer-0 cell update for t=0 (h(-1)=0) -> h0(0) into slot 0 ----
    if (warp < 13) {
        float D0[4][4], T[4][4];
#pragma unroll
        for (int nt = 0; nt < 4; nt++) {
            float2 xv = *(const float2*)(xb + 8 * nt + 2 * tg);
#pragma unroll
            for (int k = 0; k < 4; k++)
                D0[nt][k] = b0own[k >> 1] + wxo[k >> 1] * ((k & 1) ? xv.y : xv.x);
        }
        epi_tr(D0, T, j);
        epi_cell(T, c0, HC, 0, j, tg, ubase);
    }
    __syncthreads();

    for (int t = 0; t < TT; t++) {
        const __half* HCr = HC + (t & 1) * 32 * HCS;
        __half* HCw = HC + ((t + 1) & 1) * 32 * HCS;
        if (warp < 13) {
            const __half* hB = HCr + g * HCS + 2 * tg;
            float D1[4][4] = {}, D0[4][4] = {};
            uint32_t Bf[8];
#pragma unroll
            for (int nt = 0; nt < 4; nt++) {
                Bf[2 * nt]     = ld32h(hB + nt * 8 * HCS);
                Bf[2 * nt + 1] = ld32h(hB + nt * 8 * HCS + 8);
            }
#pragma unroll
            for (int c = 0; c < 7; c++) {
                int k0 = 16 * c;
                uint32_t Bn[8];
                if (c < 6) {
#pragma unroll
                    for (int nt = 0; nt < 4; nt++) {
                        Bn[2 * nt]     = ld32h(hB + nt * 8 * HCS + k0 + 16);
                        Bn[2 * nt + 1] = ld32h(hB + nt * 8 * HCS + k0 + 24);
                    }
                }
                uint32_t h00 = 0, h01 = 0, h02 = 0, h03 = 0;
                if (c < 4) {
                    h00 = ld32h(w0h + k0);     h01 = ld32h(w0h + 8 * W0S + k0);
                    h02 = ld32h(w0h + k0 + 8); h03 = ld32h(w0h + 8 * W0S + k0 + 8);
                }
#pragma unroll
                for (int nt = 0; nt < 4; nt++) {
                    uint32_t b0f = Bf[2 * nt], b1f = Bf[2 * nt + 1];
                    hmma(D1[nt], A1h[c][0], A1h[c][1], A1h[c][2], A1h[c][3], b0f, b1f);
                    if (c < 4) hmma(D0[nt], h00, h01, h02, h03, b0f, b1f);
                }
                if (c < 6) {
#pragma unroll
                    for (int q = 0; q < 8; q++) Bf[q] = Bn[q];
                }
            }
            // ---- in-register epilogue ----
            float T[4][4];
#pragma unroll
            for (int nt = 0; nt < 4; nt++)
#pragma unroll
                for (int k = 0; k < 4; k++) D1[nt][k] += b1own[k >> 1];
            epi_tr(D1, T, j);
            epi_cell(T, c1, HCw, HD, j, tg, ubase);
            if (t + 1 < TT) {
                const float* xr = xb + ((t + 1) & 1) * 32;
#pragma unroll
                for (int nt = 0; nt < 4; nt++) {
                    float2 xv = *(const float2*)(xr + 8 * nt + 2 * tg);
#pragma unroll
                    for (int k = 0; k < 4; k++)
                        D0[nt][k] += b0own[k >> 1] + wxo[k >> 1] * ((k & 1) ? xv.y : xv.x);
                }
                epi_tr(D0, T, j);
                epi_cell(T, c0, HCw, 0, j, tg, ubase);
            }
        } else {
            if (t + 2 < TT)
                xb[(t & 1) * 32 + lane] = x[(size_t)(b0 + lane) * TT + (t + 2)];
        }
        __syncthreads();
    }

    // ---- MLP head on h1(511) = HC slot 0, cols 50..99 ----
    float* tmp1 = (float*)sm;            // weights dead; reuse as scratch
    float* tmp2 = tmp1 + 1100;
    for (int item = tid; item < BT * 32; item += NTH) {
        int b = item >> 5, o = item & 31;
        float s = b1[o];
#pragma unroll 1
        for (int k = 0; k < HD; k++)
            s += __half2float(HC[b * HCS + HD + k]) * W1[o * HD + k];
        tmp1[b * 33 + o] = fmaxf(s, 0.0f);
    }
    __syncthreads();
    for (int item = tid; item < BT * 16; item += NTH) {
        int b = item >> 4, o = item & 15;
        float s = b2[o];
#pragma unroll
        for (int k = 0; k < 32; k++) s += tmp1[b * 33 + k] * W2[o * 32 + k];
        tmp2[b * 17 + o] = fmaxf(s, 0.0f);
    }
    __syncthreads();
    if (tid < BT) {
        float s = b3[0];
#pragma unroll
        for (int k = 0; k < 16; k++) s += tmp2[tid * 17 + k] * W3[k];
        out[b0 + tid] = s;
    }
}

extern "C" void kernel_launch(void* const* d_in, const int* in_sizes, int n_in,
                              void* d_out, int out_size) {
    const float* x    = (const float*)d_in[0];
    const float* Wih0 = (const float*)d_in[1];
    const float* Whh0 = (const float*)d_in[2];
    const float* bih0 = (const float*)d_in[3];
    const float* bhh0 = (const float*)d_in[4];
    const float* Wih1 = (const float*)d_in[5];
    const float* Whh1 = (const float*)d_in[6];
    const float* bih1 = (const float*)d_in[7];
    const float* bhh1 = (const float*)d_in[8];
    const float* W1   = (const float*)d_in[9];
    const float* b1   = (const float*)d_in[10];
    const float* W2   = (const float*)d_in[11];
    const float* b2   = (const float*)d_in[12];
    const float* W3   = (const float*)d_in[13];
    const float* b3   = (const float*)d_in[14];
    float* out = (float*)d_out;

    int B = in_sizes[0] / TT;
    int grid = B / BT;  // 128

    cudaFuncSetAttribute(lstm_hmma7_kernel,
                         cudaFuncAttributeMaxDynamicSharedMemorySize, SMEM_REQ);
    lstm_hmma7_kernel<<<grid, NTH, SMEM_REQ>>>(
        x, Wih0, Whh0, bih0, bhh0,
        Wih1, Whh1, bih1, bhh1,
        W1, b1, W2, b2, W3, b3, out);
}

// round 17
// speedup vs baseline: 3.8004x; 1.2229x over previous
#include <cuda_runtime.h>
#include <cuda_fp16.h>
#include <cstdint>

#define HD 50
#define BT 32
#define TT 512
#define NTH 448
#define W0S 72
#define W1S 120
#define HCS 120

#define O_W0HI 0
#define O_W1HI 29952
#define O_HC   79872           // 2 slots x 32 x 120 halves (7680 B each)
#define O_XB   95232           // 2 x 32 f32
#define SMEM_REQ 95488

__device__ __forceinline__ float tanhap(float x) {
    float y; asm("tanh.approx.f32 %0, %1;" : "=f"(y) : "f"(x)); return y;
}
__device__ __forceinline__ float sigap(float x) { return 0.5f * tanhap(0.5f * x) + 0.5f; }
__device__ __forceinline__ uint32_t ld32h(const __half* p) { return *(const uint32_t*)p; }
__device__ __forceinline__ void hmma(float* d, uint32_t a0, uint32_t a1, uint32_t a2,
                                     uint32_t a3, uint32_t b0, uint32_t b1) {
    asm volatile("mma.sync.aligned.m16n8k16.row.col.f32.f16.f16.f32 "
        "{%0,%1,%2,%3}, {%4,%5,%6,%7}, {%8,%9}, {%0,%1,%2,%3};"
        : "+f"(d[0]), "+f"(d[1]), "+f"(d[2]), "+f"(d[3])
        : "r"(a0), "r"(a1), "r"(a2), "r"(a3), "r"(b0), "r"(b1));
}

// 4x4 transpose across the 4 gate-lanes (lane bits 2,3): D[nt][k] -> T[k][gate]
__device__ __forceinline__ void epi_tr(float (&D)[4][4], float (&T)[4][4], int j) {
    const bool hi2 = j & 2, hi1 = j & 1;
#pragma unroll
    for (int k = 0; k < 4; k++) {
        float e0 = D[0][k], e1 = D[1][k], e2 = D[2][k], e3 = D[3][k];
        float s0 = hi2 ? e0 : e2, s1 = hi2 ? e1 : e3;
        float r0 = __shfl_xor_sync(0xffffffffu, s0, 8);
        float r1 = __shfl_xor_sync(0xffffffffu, s1, 8);
        e0 = hi2 ? r0 : e0; e1 = hi2 ? r1 : e1;
        e2 = hi2 ? e2 : r0; e3 = hi2 ? e3 : r1;
        float t0 = hi1 ? e0 : e1, t1 = hi1 ? e2 : e3;
        float q0 = __shfl_xor_sync(0xffffffffu, t0, 4);
        float q1 = __shfl_xor_sync(0xffffffffu, t1, 4);
        e0 = hi1 ? q0 : e0; e1 = hi1 ? e1 : q0;
        e2 = hi1 ? q1 : e2; e3 = hi1 ? e3 : q1;
        T[k][0] = e0; T[k][1] = e1; T[k][2] = e2; T[k][3] = e3;
    }
}

// cell chain for this lane's 4 cells; writes h fp16 into HCw at column base colu
__device__ __forceinline__ void epi_cell(float (&T)[4][4], float* cst, __half* HCw,
                                         int colu, int j, int tg, int ubase) {
#pragma unroll
    for (int h = 0; h < 2; h++) {
        int u = ubase + 2 * h;
#pragma unroll
        for (int k1 = 0; k1 < 2; k1++) {
            int k = 2 * h + k1;
            float i_ = sigap(T[k][0]), f_ = sigap(T[k][1]);
            float g_ = tanhap(T[k][2]), o_ = sigap(T[k][3]);
            float cv = f_ * cst[2 * h + k1] + i_ * g_;
            cst[2 * h + k1] = cv;
            if (u < HD) {
                int col = 8 * j + 2 * tg + k1;
                HCw[col * HCS + colu + u] = __float2half_rn(o_ * tanhap(cv));
            }
        }
    }
}

__global__ __launch_bounds__(NTH, 1)
void lstm_hmma8_kernel(const float* __restrict__ x,
                       const float* __restrict__ Wih0, const float* __restrict__ Whh0,
                       const float* __restrict__ bih0, const float* __restrict__ bhh0,
                       const float* __restrict__ Wih1, const float* __restrict__ Whh1,
                       const float* __restrict__ bih1, const float* __restrict__ bhh1,
                       const float* __restrict__ W1, const float* __restrict__ b1,
                       const float* __restrict__ W2, const float* __restrict__ b2,
                       const float* __restrict__ W3, const float* __restrict__ b3,
                       float* __restrict__ out) {
    extern __shared__ char sm[];
    __half* W0hi = (__half*)(sm + O_W0HI);
    __half* W1hi = (__half*)(sm + O_W1HI);
    __half* HC   = (__half*)(sm + O_HC);     // 2 slots of 3840 halves
    float*  xb   = (float*)(sm + O_XB);

    const int tid = threadIdx.x, lane = tid & 31, warp = tid >> 5;
    const int g = lane >> 2, tg = lane & 3;
    const int j = g & 3, a = g >> 2;
    const int b0 = blockIdx.x * BT;

    // ---- pack weights fp16 hi (rows r = 4u+j); W0 stride 72 (conflict-free) ----
    for (int i = tid; i < 208 * 64; i += NTH) {
        int r = i >> 6, k = i & 63;
        float v = 0.0f;
        if (r < 200 && k < HD) v = Whh0[(size_t)((r & 3) * HD + (r >> 2)) * HD + k];
        W0hi[r * W0S + k] = __float2half_rn(v);
    }
    for (int i = tid; i < 208 * 128; i += NTH) {
        int r = i >> 7, k = i & 127;
        if (k >= W1S) continue;
        float v = 0.0f;
        if (r < 200 && k < 100) {
            int row = (r & 3) * HD + (r >> 2);
            v = (k < HD) ? Wih1[(size_t)row * HD + k] : Whh1[(size_t)row * HD + (k - HD)];
        }
        W1hi[r * W1S + k] = __float2half_rn(v);
    }
    for (int i = tid; i < 2 * 32 * HCS; i += NTH) HC[i] = __half(0.f);
    if (tid < 32) xb[tid] = x[(size_t)(b0 + tid) * TT];
    else if (tid < 64) xb[32 + (tid - 32)] = x[(size_t)(b0 + tid - 32) * TT + 1];

    // per-lane own-gate constants (gate j, units ubase, ubase+2)
    const int ubase = 4 * warp + a;
    float b1own[2] = {0.f, 0.f}, b0own[2] = {0.f, 0.f}, wxo[2] = {0.f, 0.f};
    if (warp < 13) {
#pragma unroll
        for (int h = 0; h < 2; h++) {
            int u = ubase + 2 * h;
            if (u < HD) {
                int r = j * HD + u;
                b1own[h] = bih1[r] + bhh1[r];
                b0own[h] = bih0[r] + bhh0[r];
                wxo[h]   = Wih0[r];
            }
        }
    }
    float c1[4] = {0.f, 0.f, 0.f, 0.f}, c0[4] = {0.f, 0.f, 0.f, 0.f};
    __syncthreads();

    // ---- hoist layer-1 A-hi fragments ----
    uint32_t A1h[7][4];
    if (warp < 13) {
        const __half* w1 = W1hi + (warp * 16 + g) * W1S + 2 * tg;
#pragma unroll
        for (int c = 0; c < 7; c++) {
            int k0 = 16 * c;
            A1h[c][0] = ld32h(w1 + k0);     A1h[c][1] = ld32h(w1 + 8 * W1S + k0);
            A1h[c][2] = ld32h(w1 + k0 + 8); A1h[c][3] = ld32h(w1 + 8 * W1S + k0 + 8);
        }
    }
    const __half* w0h = W0hi + (warp * 16 + g) * W0S + 2 * tg;

    // ---- prologue: layer-0 cell update for t=0 (h(-1)=0) -> h0(0) into slot 0 ----
    if (warp < 13) {
        float D0[4][4], T[4][4];
#pragma unroll
        for (int nt = 0; nt < 4; nt++) {
            float2 xv = *(const float2*)(xb + 8 * nt + 2 * tg);
#pragma unroll
            for (int k = 0; k < 4; k++)
                D0[nt][k] = b0own[k >> 1] + wxo[k >> 1] * ((k & 1) ? xv.y : xv.x);
        }
        epi_tr(D0, T, j);
        epi_cell(T, c0, HC, 0, j, tg, ubase);
    }
    __syncthreads();

    for (int t = 0; t < TT; t++) {
        const __half* HCr = HC + (t & 1) * 32 * HCS;
        __half* HCw = HC + ((t + 1) & 1) * 32 * HCS;
        if (warp < 13) {
            const __half* hB = HCr + g * HCS + 2 * tg;
            float D1[4][4] = {}, D0[4][4] = {};
            uint32_t Bf[8];
#pragma unroll
            for (int nt = 0; nt < 4; nt++) {
                Bf[2 * nt]     = ld32h(hB + nt * 8 * HCS);
                Bf[2 * nt + 1] = ld32h(hB + nt * 8 * HCS + 8);
            }
#pragma unroll
            for (int c = 0; c < 7; c++) {
                int k0 = 16 * c;
                uint32_t Bn[8];
                if (c < 6) {
#pragma unroll
                    for (int nt = 0; nt < 4; nt++) {
                        Bn[2 * nt]     = ld32h(hB + nt * 8 * HCS + k0 + 16);
                        Bn[2 * nt + 1] = ld32h(hB + nt * 8 * HCS + k0 + 24);
                    }
                }
                uint32_t h00 = 0, h01 = 0, h02 = 0, h03 = 0;
                if (c < 4) {
                    h00 = ld32h(w0h + k0);     h01 = ld32h(w0h + 8 * W0S + k0);
                    h02 = ld32h(w0h + k0 + 8); h03 = ld32h(w0h + 8 * W0S + k0 + 8);
                }
#pragma unroll
                for (int nt = 0; nt < 4; nt++) {
                    uint32_t b0f = Bf[2 * nt], b1f = Bf[2 * nt + 1];
                    hmma(D1[nt], A1h[c][0], A1h[c][1], A1h[c][2], A1h[c][3], b0f, b1f);
                    if (c < 4) hmma(D0[nt], h00, h01, h02, h03, b0f, b1f);
                }
                if (c < 6) {
#pragma unroll
                    for (int q = 0; q < 8; q++) Bf[q] = Bn[q];
                }
            }
            // ---- in-register epilogue ----
            float T[4][4];
#pragma unroll
            for (int nt = 0; nt < 4; nt++)
#pragma unroll
                for (int k = 0; k < 4; k++) D1[nt][k] += b1own[k >> 1];
            epi_tr(D1, T, j);
            epi_cell(T, c1, HCw, HD, j, tg, ubase);
            if (t + 1 < TT) {
                const float* xr = xb + ((t + 1) & 1) * 32;
#pragma unroll
                for (int nt = 0; nt < 4; nt++) {
                    float2 xv = *(const float2*)(xr + 8 * nt + 2 * tg);
#pragma unroll
                    for (int k = 0; k < 4; k++)
                        D0[nt][k] += b0own[k >> 1] + wxo[k >> 1] * ((k & 1) ? xv.y : xv.x);
                }
                epi_tr(D0, T, j);
                epi_cell(T, c0, HCw, 0, j, tg, ubase);
            }
        } else {
            if (t + 2 < TT)
                xb[(t & 1) * 32 + lane] = x[(size_t)(b0 + lane) * TT + (t + 2)];
        }
        __syncthreads();
    }

    // ---- MLP head on h1(511) = HC slot 0, cols 50..99 ----
    float* tmp1 = (float*)sm;            // weights dead; reuse as scratch
    float* tmp2 = tmp1 + 1100;
    for (int item = tid; item < BT * 32; item += NTH) {
        int b = item >> 5, o = item & 31;
        float s = b1[o];
#pragma unroll 1
        for (int k = 0; k < HD; k++)
            s += __half2float(HC[b * HCS + HD + k]) * W1[o * HD + k];
        tmp1[b * 33 + o] = fmaxf(s, 0.0f);
    }
    __syncthreads();
    for (int item = tid; item < BT * 16; item += NTH) {
        int b = item >> 4, o = item & 15;
        float s = b2[o];
#pragma unroll
        for (int k = 0; k < 32; k++) s += tmp1[b * 33 + k] * W2[o * 32 + k];
        tmp2[b * 17 + o] = fmaxf(s, 0.0f);
    }
    __syncthreads();
    if (tid < BT) {
        float s = b3[0];
#pragma unroll
        for (int k = 0; k < 16; k++) s += tmp2[tid * 17 + k] * W3[k];
        out[b0 + tid] = s;
    }
}

extern "C" void kernel_launch(void* const* d_in, const int* in_sizes, int n_in,
                              void* d_out, int out_size) {
    const float* x    = (const float*)d_in[0];
    const float* Wih0 = (const float*)d_in[1];
    const float* Whh0 = (const float*)d_in[2];
    const float* bih0 = (const float*)d_in[3];
    const float* bhh0 = (const float*)d_in[4];
    const float* Wih1 = (const float*)d_in[5];
    const float* Whh1 = (const float*)d_in[6];
    const float* bih1 = (const float*)d_in[7];
    const float* bhh1 = (const float*)d_in[8];
    const float* W1   = (const float*)d_in[9];
    const float* b1   = (const float*)d_in[10];
    const float* W2   = (const float*)d_in[11];
    const float* b2   = (const float*)d_in[12];
    const float* W3   = (const float*)d_in[13];
    const float* b3   = (const float*)d_in[14];
    float* out = (float*)d_out;

    int B = in_sizes[0] / TT;
    int grid = B / BT;  // 128

    cudaFuncSetAttribute(lstm_hmma8_kernel,
                         cudaFuncAttributeMaxDynamicSharedMemorySize, SMEM_REQ);
    lstm_hmma8_kernel<<<grid, NTH, SMEM_REQ>>>(
        x, Wih0, Whh0, bih0, bhh0,
        Wih1, Whh1, bih1, bhh1,
        W1, b1, W2, b2, W3, b3, out);
}